// round 1
// baseline (speedup 1.0000x reference)
#include <cuda_runtime.h>
#include <math.h>

#define CS 1024
#define NI 1024
#define NJ 1024
#define NH 16
#define ND 64
#define CZ 128

// ---------------- scratch (device globals; no allocation allowed) ----------
__device__ float g_q[NI * CS];
__device__ float g_k[NJ * CS];
__device__ float g_v[NJ * CS];
__device__ float g_gt[NI * CS];
__device__ float g_o[NI * CS];
__device__ float g_z[(size_t)NH * NI * NJ];   // layout [h][i*NJ + j], 64 MB

// ---------------- generic NT GEMM: C[M,N] = A[M,K] * B[N,K]^T ---------------
// BM=BN=64, BK=16, 256 threads, 4x4 per-thread tile, fp32.
template <int HAS_BIAS, int SIGMOID, int HAS_A2>
__global__ __launch_bounds__(256) void gemm_nt(
    const float* __restrict__ A, const float* __restrict__ A2,
    const float* __restrict__ B, const float* __restrict__ bias,
    float* __restrict__ C)
{
    const int K = CS, N = CS;
    __shared__ float As[16][68];
    __shared__ float Bs[16][68];

    const int tid = threadIdx.x;
    const int bm = blockIdx.y * 64;
    const int bn = blockIdx.x * 64;
    const int lr = tid >> 2;          // 0..63  (row within tile)
    const int lc = (tid & 3) << 2;    // 0,4,8,12 (k-chunk)
    const int tm = (tid >> 4) << 2;   // 0..60
    const int tn = (tid & 15) << 2;   // 0..60

    float acc[4][4] = {};

    for (int k0 = 0; k0 < K; k0 += 16) {
        float4 av = *(const float4*)(A + (size_t)(bm + lr) * K + k0 + lc);
        if (HAS_A2) {
            float4 a2 = *(const float4*)(A2 + (size_t)(bm + lr) * K + k0 + lc);
            av.x *= a2.x; av.y *= a2.y; av.z *= a2.z; av.w *= a2.w;
        }
        float4 bv = *(const float4*)(B + (size_t)(bn + lr) * K + k0 + lc);
        As[lc + 0][lr] = av.x; As[lc + 1][lr] = av.y;
        As[lc + 2][lr] = av.z; As[lc + 3][lr] = av.w;
        Bs[lc + 0][lr] = bv.x; Bs[lc + 1][lr] = bv.y;
        Bs[lc + 2][lr] = bv.z; Bs[lc + 3][lr] = bv.w;
        __syncthreads();
#pragma unroll
        for (int c = 0; c < 16; c++) {
            float4 a = *(const float4*)&As[c][tm];
            float4 b = *(const float4*)&Bs[c][tn];
            float ar[4] = {a.x, a.y, a.z, a.w};
            float br[4] = {b.x, b.y, b.z, b.w};
#pragma unroll
            for (int i = 0; i < 4; i++)
#pragma unroll
                for (int j = 0; j < 4; j++)
                    acc[i][j] = fmaf(ar[i], br[j], acc[i][j]);
        }
        __syncthreads();
    }

#pragma unroll
    for (int i = 0; i < 4; i++) {
        float4 r;
        float* pr = &r.x;
#pragma unroll
        for (int j = 0; j < 4; j++) {
            float v = acc[i][j];
            if (HAS_BIAS) v += bias[bn + tn + j];
            if (SIGMOID) v = 1.0f / (1.0f + __expf(-v));
            pr[j] = v;
        }
        *(float4*)(C + (size_t)(bm + tm + i) * N + bn + tn) = r;
    }
}

// ---------------- z projection: z[h, m] = sum_c bias[m, c] * Wz[c, h] -------
// + key mask. 64 (i,j)-pairs per block; outputs staged through smem so the
// [h][m] stores are coalesced.
__global__ __launch_bounds__(256) void z_kernel(
    const float* __restrict__ bias, const float* __restrict__ Wz,
    const float* __restrict__ mask, float* __restrict__ z)
{
    __shared__ float sb[64][132];     // bias tile, padded
    __shared__ float wzT[16][128];    // Wz transposed: wzT[h][c]
    __shared__ float outs[64][17];    // output transpose staging

    const int tid = threadIdx.x;
    const int m0 = blockIdx.x * 64;

    for (int idx = tid; idx < CZ * NH; idx += 256) {
        int c = idx >> 4, h = idx & 15;
        wzT[h][c] = Wz[c * NH + h];
    }
    for (int f = tid; f < 64 * 32; f += 256) {
        int r = f >> 5, c4 = (f & 31) << 2;
        float4 v = *(const float4*)(bias + (size_t)(m0 + r) * CZ + c4);
        *(float4*)&sb[r][c4] = v;
    }
    __syncthreads();

    const int pg = tid >> 4;   // pair group 0..15 (4 pairs each)
    const int h  = tid & 15;
    float acc[4] = {0.f, 0.f, 0.f, 0.f};
#pragma unroll
    for (int c4 = 0; c4 < 128; c4 += 4) {
        float4 w = *(const float4*)&wzT[h][c4];
#pragma unroll
        for (int p = 0; p < 4; p++) {
            float4 b = *(const float4*)&sb[pg * 4 + p][c4];
            acc[p] += b.x * w.x + b.y * w.y + b.z * w.z + b.w * w.w;
        }
    }
#pragma unroll
    for (int p = 0; p < 4; p++) outs[pg * 4 + p][h] = acc[p];
    __syncthreads();

    for (int lin = tid; lin < 1024; lin += 256) {
        int hh = lin >> 6, mm = lin & 63;
        int m = m0 + mm;
        float val = outs[mm][hh] + (1.0f - mask[m & (NJ - 1)]) * (-1000000.0f);
        z[(size_t)hh * ((size_t)NI * NJ) + m] = val;
    }
}

// ---------------- attention: one block = (8 i-rows, 1 head) ----------------
__global__ __launch_bounds__(256) void attn_kernel(
    const float* __restrict__ q, const float* __restrict__ k,
    const float* __restrict__ v, const float* __restrict__ z,
    float* __restrict__ o)
{
    __shared__ float4 qs[8][16];          // 2 KB
    __shared__ float  lg[8][1024];        // 32 KB logits/probs
    __shared__ float  inv_s[8];
    __shared__ float  part[4][8][64];     // 8 KB

    const int tid = threadIdx.x;
    const int i0 = blockIdx.x * 8;
    const int h  = blockIdx.y;
    const float* zh = z + (size_t)h * ((size_t)NI * NJ);

    if (tid < 128) {
        int ii = tid >> 4, d4 = tid & 15;
        qs[ii][d4] = *(const float4*)(q + (size_t)(i0 + ii) * CS + h * ND + d4 * 4);
    }
    __syncthreads();

    // phase 1: logits = q.k / 8 + z
    for (int jj = 0; jj < 4; jj++) {
        int j = tid + jj * 256;
        float4 kr[16];
        const float4* kp = (const float4*)(k + (size_t)j * CS + h * ND);
#pragma unroll
        for (int d = 0; d < 16; d++) kr[d] = kp[d];
#pragma unroll
        for (int ii = 0; ii < 8; ii++) {
            float s = 0.f;
#pragma unroll
            for (int d = 0; d < 16; d++) {
                float4 a = qs[ii][d];
                s += a.x * kr[d].x + a.y * kr[d].y + a.z * kr[d].z + a.w * kr[d].w;
            }
            lg[ii][j] = s * 0.125f + zh[(size_t)(i0 + ii) * NJ + j];
        }
    }
    __syncthreads();

    // softmax: warp w handles row w (stride-4 float4 reads -> <=4-way conflict)
    {
        const int w = tid >> 5, lane = tid & 31;
        float mx = -1e30f;
        float4 vals[8];
#pragma unroll
        for (int kk = 0; kk < 8; kk++) {
            vals[kk] = *(const float4*)&lg[w][lane * 4 + kk * 128];
            mx = fmaxf(mx, fmaxf(fmaxf(vals[kk].x, vals[kk].y),
                                 fmaxf(vals[kk].z, vals[kk].w)));
        }
#pragma unroll
        for (int s = 16; s > 0; s >>= 1)
            mx = fmaxf(mx, __shfl_xor_sync(0xffffffffu, mx, s));
        float sum = 0.f;
#pragma unroll
        for (int kk = 0; kk < 8; kk++) {
            float4 e;
            e.x = __expf(vals[kk].x - mx);
            e.y = __expf(vals[kk].y - mx);
            e.z = __expf(vals[kk].z - mx);
            e.w = __expf(vals[kk].w - mx);
            sum += e.x + e.y + e.z + e.w;
            *(float4*)&lg[w][lane * 4 + kk * 128] = e;
        }
#pragma unroll
        for (int s = 16; s > 0; s >>= 1)
            sum += __shfl_xor_sync(0xffffffffu, sum, s);
        if (lane == 0) inv_s[w] = 1.0f / sum;
    }
    __syncthreads();

    // phase 2: o[ii][d] = sum_j p * v   (quarter of j per thread group)
    {
        const int d = tid & 63, qt = tid >> 6;
        float acc[8] = {};
        const float* vp = v + h * ND + d;
        for (int j4 = qt * 64; j4 < qt * 64 + 64; j4++) {
            int j = j4 * 4;
            float v0 = vp[(size_t)(j + 0) * CS];
            float v1 = vp[(size_t)(j + 1) * CS];
            float v2 = vp[(size_t)(j + 2) * CS];
            float v3 = vp[(size_t)(j + 3) * CS];
#pragma unroll
            for (int ii = 0; ii < 8; ii++) {
                float4 p = *(const float4*)&lg[ii][j];
                acc[ii] += p.x * v0 + p.y * v1 + p.z * v2 + p.w * v3;
            }
        }
#pragma unroll
        for (int ii = 0; ii < 8; ii++) part[qt][ii][d] = acc[ii];
    }
    __syncthreads();

    for (int lin = tid; lin < 512; lin += 256) {
        int ii = lin >> 6, dd = lin & 63;
        float s = part[0][ii][dd] + part[1][ii][dd] +
                  part[2][ii][dd] + part[3][ii][dd];
        o[(size_t)(i0 + ii) * CS + h * ND + dd] = s * inv_s[ii];
    }
}

// ---------------------------------------------------------------------------
extern "C" void kernel_launch(void* const* d_in, const int* in_sizes, int n_in,
                              void* d_out, int out_size)
{
    (void)in_sizes; (void)n_in; (void)out_size;
    const float* s    = (const float*)d_in[0];
    const float* k_in = (const float*)d_in[1];
    const float* mask = (const float*)d_in[2];
    const float* bias = (const float*)d_in[3];
    const float* Wq   = (const float*)d_in[4];
    const float* bq   = (const float*)d_in[5];
    const float* Wk   = (const float*)d_in[6];
    const float* Wv   = (const float*)d_in[7];
    const float* Wg   = (const float*)d_in[8];
    const float* Wo   = (const float*)d_in[9];
    const float* Wz   = (const float*)d_in[10];
    // d_in[11] = multiplicity (always 1 for this problem)
    float* out = (float*)d_out;

    float *q, *k, *v, *g, *o, *z;
    cudaGetSymbolAddress((void**)&q, g_q);
    cudaGetSymbolAddress((void**)&k, g_k);
    cudaGetSymbolAddress((void**)&v, g_v);
    cudaGetSymbolAddress((void**)&g, g_gt);
    cudaGetSymbolAddress((void**)&o, g_o);
    cudaGetSymbolAddress((void**)&z, g_z);

    dim3 ggrid(16, 16), gblk(256);
    // projections
    gemm_nt<1, 0, 0><<<ggrid, gblk>>>(s,    nullptr, Wq, bq,      q);
    gemm_nt<0, 0, 0><<<ggrid, gblk>>>(k_in, nullptr, Wk, nullptr, k);
    gemm_nt<0, 0, 0><<<ggrid, gblk>>>(k_in, nullptr, Wv, nullptr, v);
    gemm_nt<0, 1, 0><<<ggrid, gblk>>>(s,    nullptr, Wg, nullptr, g);
    // pair-bias projection + mask
    z_kernel<<<(NI * NJ) / 64, 256>>>(bias, Wz, mask, z);
    // attention
    attn_kernel<<<dim3(NI / 8, NH), 256>>>(q, k, v, z, o);
    // output projection with gating: out = (g .* o) @ Wo^T
    gemm_nt<0, 0, 1><<<ggrid, gblk>>>(o, g, Wo, nullptr, out);
}

// round 2
// speedup vs baseline: 1.3286x; 1.3286x over previous
#include <cuda_runtime.h>
#include <math.h>

#define CS 1024
#define NI 1024
#define NJ 1024
#define NH 16
#define ND 64
#define CZ 128

// ---------------- scratch (device globals; no allocation allowed) ----------
__device__ float g_q[NI * CS];
__device__ float g_k[NJ * CS];
__device__ float g_v[NJ * CS];
__device__ float g_gt[NI * CS];
__device__ float g_o[NI * CS];
__device__ float g_z[(size_t)NH * NI * NJ];   // layout [h][i*NJ + j], 64 MB

// ---------------- batched projection GEMM ----------------------------------
// One launch computes all 4 independent projections (q,k,v,g) selected by
// blockIdx.z, so the grid is 1024 blocks instead of 4x256 -> full occupancy.
// C[M,N] = A[M,K] * B[N,K]^T  (+bias / sigmoid per projection)
__global__ __launch_bounds__(256) void proj4(
    const float* __restrict__ s, const float* __restrict__ k_in,
    const float* __restrict__ Wq, const float* __restrict__ bq,
    const float* __restrict__ Wk, const float* __restrict__ Wv,
    const float* __restrict__ Wg,
    float* __restrict__ q, float* __restrict__ k,
    float* __restrict__ v, float* __restrict__ g)
{
    const int K = CS, N = CS;
    __shared__ float As[16][68];
    __shared__ float Bs[16][68];

    const float* A;
    const float* B;
    const float* bias = nullptr;
    float* C;
    bool sig = false;
    switch (blockIdx.z) {
        case 0: A = s;    B = Wq; bias = bq; C = q; break;
        case 1: A = k_in; B = Wk;            C = k; break;
        case 2: A = k_in; B = Wv;            C = v; break;
        default: A = s;   B = Wg;            C = g; sig = true; break;
    }

    const int tid = threadIdx.x;
    const int bm = blockIdx.y * 64;
    const int bn = blockIdx.x * 64;
    const int lr = tid >> 2;
    const int lc = (tid & 3) << 2;
    const int tm = (tid >> 4) << 2;
    const int tn = (tid & 15) << 2;

    float acc[4][4] = {};

    for (int k0 = 0; k0 < K; k0 += 16) {
        float4 av = *(const float4*)(A + (size_t)(bm + lr) * K + k0 + lc);
        float4 bv = *(const float4*)(B + (size_t)(bn + lr) * K + k0 + lc);
        As[lc + 0][lr] = av.x; As[lc + 1][lr] = av.y;
        As[lc + 2][lr] = av.z; As[lc + 3][lr] = av.w;
        Bs[lc + 0][lr] = bv.x; Bs[lc + 1][lr] = bv.y;
        Bs[lc + 2][lr] = bv.z; Bs[lc + 3][lr] = bv.w;
        __syncthreads();
#pragma unroll
        for (int c = 0; c < 16; c++) {
            float4 a = *(const float4*)&As[c][tm];
            float4 b = *(const float4*)&Bs[c][tn];
            float ar[4] = {a.x, a.y, a.z, a.w};
            float br[4] = {b.x, b.y, b.z, b.w};
#pragma unroll
            for (int i = 0; i < 4; i++)
#pragma unroll
                for (int j = 0; j < 4; j++)
                    acc[i][j] = fmaf(ar[i], br[j], acc[i][j]);
        }
        __syncthreads();
    }

#pragma unroll
    for (int i = 0; i < 4; i++) {
        float4 r;
        float* pr = &r.x;
#pragma unroll
        for (int j = 0; j < 4; j++) {
            float vv = acc[i][j];
            if (bias) vv += bias[bn + tn + j];
            if (sig) vv = 1.0f / (1.0f + __expf(-vv));
            pr[j] = vv;
        }
        *(float4*)(C + (size_t)(bm + tm + i) * N + bn + tn) = r;
    }
}

// ---------------- final gating GEMM: out = (g .* o) @ Wo^T ------------------
__global__ __launch_bounds__(256) void gemm_gated(
    const float* __restrict__ A, const float* __restrict__ A2,
    const float* __restrict__ B, float* __restrict__ C)
{
    const int K = CS, N = CS;
    __shared__ float As[16][68];
    __shared__ float Bs[16][68];

    const int tid = threadIdx.x;
    const int bm = blockIdx.y * 64;
    const int bn = blockIdx.x * 64;
    const int lr = tid >> 2;
    const int lc = (tid & 3) << 2;
    const int tm = (tid >> 4) << 2;
    const int tn = (tid & 15) << 2;

    float acc[4][4] = {};

    for (int k0 = 0; k0 < K; k0 += 16) {
        float4 av = *(const float4*)(A + (size_t)(bm + lr) * K + k0 + lc);
        float4 a2 = *(const float4*)(A2 + (size_t)(bm + lr) * K + k0 + lc);
        av.x *= a2.x; av.y *= a2.y; av.z *= a2.z; av.w *= a2.w;
        float4 bv = *(const float4*)(B + (size_t)(bn + lr) * K + k0 + lc);
        As[lc + 0][lr] = av.x; As[lc + 1][lr] = av.y;
        As[lc + 2][lr] = av.z; As[lc + 3][lr] = av.w;
        Bs[lc + 0][lr] = bv.x; Bs[lc + 1][lr] = bv.y;
        Bs[lc + 2][lr] = bv.z; Bs[lc + 3][lr] = bv.w;
        __syncthreads();
#pragma unroll
        for (int c = 0; c < 16; c++) {
            float4 a = *(const float4*)&As[c][tm];
            float4 b = *(const float4*)&Bs[c][tn];
            float ar[4] = {a.x, a.y, a.z, a.w};
            float br[4] = {b.x, b.y, b.z, b.w};
#pragma unroll
            for (int i = 0; i < 4; i++)
#pragma unroll
                for (int j = 0; j < 4; j++)
                    acc[i][j] = fmaf(ar[i], br[j], acc[i][j]);
        }
        __syncthreads();
    }

#pragma unroll
    for (int i = 0; i < 4; i++) {
        float4 r;
        r.x = acc[i][0]; r.y = acc[i][1]; r.z = acc[i][2]; r.w = acc[i][3];
        *(float4*)(C + (size_t)(bm + tm + i) * N + bn + tn) = r;
    }
}

// ---------------- z projection: z[h, m] = sum_c bias[m, c] * Wz[c, h] -------
// wzT padded to 132 floats/row: row stride 528B spreads the 16 h-rows across
// bank groups (was 512B -> 16-way conflict on every LDS.128).
__global__ __launch_bounds__(256) void z_kernel(
    const float* __restrict__ bias, const float* __restrict__ Wz,
    const float* __restrict__ mask, float* __restrict__ z)
{
    __shared__ float sb[64][132];     // bias tile, padded
    __shared__ float wzT[16][132];    // Wz transposed + padded
    __shared__ float outs[64][17];    // output transpose staging

    const int tid = threadIdx.x;
    const int m0 = blockIdx.x * 64;

    for (int idx = tid; idx < CZ * NH; idx += 256) {
        int c = idx >> 4, h = idx & 15;
        wzT[h][c] = Wz[c * NH + h];
    }
    for (int f = tid; f < 64 * 32; f += 256) {
        int r = f >> 5, c4 = (f & 31) << 2;
        float4 v = *(const float4*)(bias + (size_t)(m0 + r) * CZ + c4);
        *(float4*)&sb[r][c4] = v;
    }
    __syncthreads();

    const int pg = tid >> 4;   // pair group 0..15 (4 pairs each)
    const int h  = tid & 15;
    float acc[4] = {0.f, 0.f, 0.f, 0.f};
#pragma unroll
    for (int c4 = 0; c4 < 128; c4 += 4) {
        float4 w = *(const float4*)&wzT[h][c4];
#pragma unroll
        for (int p = 0; p < 4; p++) {
            float4 b = *(const float4*)&sb[pg * 4 + p][c4];
            acc[p] += b.x * w.x + b.y * w.y + b.z * w.z + b.w * w.w;
        }
    }
#pragma unroll
    for (int p = 0; p < 4; p++) outs[pg * 4 + p][h] = acc[p];
    __syncthreads();

    for (int lin = tid; lin < 1024; lin += 256) {
        int hh = lin >> 6, mm = lin & 63;
        int m = m0 + mm;
        float val = outs[mm][hh] + (1.0f - mask[m & (NJ - 1)]) * (-1000000.0f);
        z[(size_t)hh * ((size_t)NI * NJ) + m] = val;
    }
}

// ---------------- attention: one block = (8 i-rows, 1 head) ----------------
__global__ __launch_bounds__(256) void attn_kernel(
    const float* __restrict__ q, const float* __restrict__ k,
    const float* __restrict__ v, const float* __restrict__ z,
    float* __restrict__ o)
{
    __shared__ float4 qs[8][16];
    __shared__ float  lg[8][1024];
    __shared__ float  inv_s[8];
    __shared__ float  part[4][8][64];

    const int tid = threadIdx.x;
    const int i0 = blockIdx.x * 8;
    const int h  = blockIdx.y;
    const float* zh = z + (size_t)h * ((size_t)NI * NJ);

    if (tid < 128) {
        int ii = tid >> 4, d4 = tid & 15;
        qs[ii][d4] = *(const float4*)(q + (size_t)(i0 + ii) * CS + h * ND + d4 * 4);
    }
    __syncthreads();

    // phase 1: logits = q.k / 8 + z
    for (int jj = 0; jj < 4; jj++) {
        int j = tid + jj * 256;
        float4 kr[16];
        const float4* kp = (const float4*)(k + (size_t)j * CS + h * ND);
#pragma unroll
        for (int d = 0; d < 16; d++) kr[d] = kp[d];
#pragma unroll
        for (int ii = 0; ii < 8; ii++) {
            float s = 0.f;
#pragma unroll
            for (int d = 0; d < 16; d++) {
                float4 a = qs[ii][d];
                s += a.x * kr[d].x + a.y * kr[d].y + a.z * kr[d].z + a.w * kr[d].w;
            }
            lg[ii][j] = s * 0.125f + zh[(size_t)(i0 + ii) * NJ + j];
        }
    }
    __syncthreads();

    // softmax: warp w handles row w
    {
        const int w = tid >> 5, lane = tid & 31;
        float mx = -1e30f;
        float4 vals[8];
#pragma unroll
        for (int kk = 0; kk < 8; kk++) {
            vals[kk] = *(const float4*)&lg[w][lane * 4 + kk * 128];
            mx = fmaxf(mx, fmaxf(fmaxf(vals[kk].x, vals[kk].y),
                                 fmaxf(vals[kk].z, vals[kk].w)));
        }
#pragma unroll
        for (int s = 16; s > 0; s >>= 1)
            mx = fmaxf(mx, __shfl_xor_sync(0xffffffffu, mx, s));
        float sum = 0.f;
#pragma unroll
        for (int kk = 0; kk < 8; kk++) {
            float4 e;
            e.x = __expf(vals[kk].x - mx);
            e.y = __expf(vals[kk].y - mx);
            e.z = __expf(vals[kk].z - mx);
            e.w = __expf(vals[kk].w - mx);
            sum += e.x + e.y + e.z + e.w;
            *(float4*)&lg[w][lane * 4 + kk * 128] = e;
        }
#pragma unroll
        for (int s = 16; s > 0; s >>= 1)
            sum += __shfl_xor_sync(0xffffffffu, sum, s);
        if (lane == 0) inv_s[w] = 1.0f / sum;
    }
    __syncthreads();

    // phase 2: o[ii][d] = sum_j p * v
    {
        const int d = tid & 63, qt = tid >> 6;
        float acc[8] = {};
        const float* vp = v + h * ND + d;
        for (int j4 = qt * 64; j4 < qt * 64 + 64; j4++) {
            int j = j4 * 4;
            float v0 = vp[(size_t)(j + 0) * CS];
            float v1 = vp[(size_t)(j + 1) * CS];
            float v2 = vp[(size_t)(j + 2) * CS];
            float v3 = vp[(size_t)(j + 3) * CS];
#pragma unroll
            for (int ii = 0; ii < 8; ii++) {
                float4 p = *(const float4*)&lg[ii][j];
                acc[ii] += p.x * v0 + p.y * v1 + p.z * v2 + p.w * v3;
            }
        }
#pragma unroll
        for (int ii = 0; ii < 8; ii++) part[qt][ii][d] = acc[ii];
    }
    __syncthreads();

    for (int lin = tid; lin < 512; lin += 256) {
        int ii = lin >> 6, dd = lin & 63;
        float s = part[0][ii][dd] + part[1][ii][dd] +
                  part[2][ii][dd] + part[3][ii][dd];
        o[(size_t)(i0 + ii) * CS + h * ND + dd] = s * inv_s[ii];
    }
}

// ---------------------------------------------------------------------------
extern "C" void kernel_launch(void* const* d_in, const int* in_sizes, int n_in,
                              void* d_out, int out_size)
{
    (void)in_sizes; (void)n_in; (void)out_size;
    const float* s    = (const float*)d_in[0];
    const float* k_in = (const float*)d_in[1];
    const float* mask = (const float*)d_in[2];
    const float* bias = (const float*)d_in[3];
    const float* Wq   = (const float*)d_in[4];
    const float* bq   = (const float*)d_in[5];
    const float* Wk   = (const float*)d_in[6];
    const float* Wv   = (const float*)d_in[7];
    const float* Wg   = (const float*)d_in[8];
    const float* Wo   = (const float*)d_in[9];
    const float* Wz   = (const float*)d_in[10];
    float* out = (float*)d_out;

    float *q, *k, *v, *g, *o, *z;
    cudaGetSymbolAddress((void**)&q, g_q);
    cudaGetSymbolAddress((void**)&k, g_k);
    cudaGetSymbolAddress((void**)&v, g_v);
    cudaGetSymbolAddress((void**)&g, g_gt);
    cudaGetSymbolAddress((void**)&o, g_o);
    cudaGetSymbolAddress((void**)&z, g_z);

    // all 4 projections in ONE launch (grid-starvation fix)
    proj4<<<dim3(16, 16, 4), 256>>>(s, k_in, Wq, bq, Wk, Wv, Wg, q, k, v, g);
    // pair-bias projection + mask (bank-conflict fix)
    z_kernel<<<(NI * NJ) / 64, 256>>>(bias, Wz, mask, z);
    // attention
    attn_kernel<<<dim3(NI / 8, NH), 256>>>(q, k, v, z, o);
    // output projection with gating
    gemm_gated<<<dim3(16, 16), 256>>>(o, g, Wo, out);
}

// round 7
// speedup vs baseline: 1.9195x; 1.4447x over previous
#include <cuda_runtime.h>
#include <cuda_bf16.h>
#include <stdint.h>
#include <math.h>

#define CS 1024
#define NI 1024
#define NJ 1024
#define NH 16
#define ND 64
#define CZ 128

// ---------------- scratch (device globals; no allocation allowed) ----------
__device__ float g_q[NI * CS];
__device__ float g_k[NJ * CS];
__device__ float g_v[NJ * CS];
__device__ float g_gt[NI * CS];
__device__ float g_o[NI * CS];
__device__ float g_z[(size_t)NH * NI * NJ];   // layout [h][i*NJ + j], 64 MB

// ===================== mma.sync helpers (sm_80+ PTX, no 'a' gate) ==========
__device__ __forceinline__ uint32_t smem_u32(const void* p) {
    uint32_t r;
    asm("{ .reg .u64 t; cvta.to.shared.u64 t, %1; cvt.u32.u64 %0, t; }"
        : "=r"(r) : "l"(p));
    return r;
}
__device__ __forceinline__ void ldsm4(uint32_t* r, uint32_t a) {
    asm volatile("ldmatrix.sync.aligned.m8n8.x4.shared.b16 {%0,%1,%2,%3}, [%4];"
                 : "=r"(r[0]), "=r"(r[1]), "=r"(r[2]), "=r"(r[3]) : "r"(a));
}
__device__ __forceinline__ void mma_bf16(float* d, const uint32_t* a,
                                         uint32_t b0, uint32_t b1) {
    asm volatile(
        "mma.sync.aligned.m16n8k16.row.col.f32.bf16.bf16.f32 "
        "{%0,%1,%2,%3}, {%4,%5,%6,%7}, {%8,%9}, {%0,%1,%2,%3};"
        : "+f"(d[0]), "+f"(d[1]), "+f"(d[2]), "+f"(d[3])
        : "r"(a[0]), "r"(a[1]), "r"(a[2]), "r"(a[3]), "r"(b0), "r"(b1));
}
__device__ __forceinline__ uint32_t pack2(__nv_bfloat16 a, __nv_bfloat16 b) {
    return (uint32_t)__bfloat16_as_ushort(a) |
           ((uint32_t)__bfloat16_as_ushort(b) << 16);
}
// fp32x4 -> bf16 hi (8B) + bf16 lo residual (8B)
__device__ __forceinline__ void split4(float4 v, uint2* hi, uint2* lo) {
    __nv_bfloat16 h0 = __float2bfloat16_rn(v.x);
    __nv_bfloat16 h1 = __float2bfloat16_rn(v.y);
    __nv_bfloat16 h2 = __float2bfloat16_rn(v.z);
    __nv_bfloat16 h3 = __float2bfloat16_rn(v.w);
    hi->x = pack2(h0, h1); hi->y = pack2(h2, h3);
    lo->x = pack2(__float2bfloat16_rn(v.x - __bfloat162float(h0)),
                  __float2bfloat16_rn(v.y - __bfloat162float(h1)));
    lo->y = pack2(__float2bfloat16_rn(v.z - __bfloat162float(h2)),
                  __float2bfloat16_rn(v.w - __bfloat162float(h3)));
}

// ============ bf16-split mma GEMM: C[128,64] tile of A[M,K]*B[N,K]^T =======
// 256 threads, 8 warps (4m x 2n), warp tile 32x32, BK=32, K=1024.
// mode: 0 plain, 1 +bias, 2 sigmoid. A2: optional elementwise multiplier.
#define ASTR 80   // smem row stride bytes (32 bf16 = 64B data + 16B pad)

__device__ __forceinline__ void gemm_mma_body(
    const float* __restrict__ A, const float* __restrict__ A2,
    const float* __restrict__ Bw, const float* __restrict__ bias, int mode,
    float* __restrict__ C, int bm, int bn)
{
    __shared__ __align__(16) uint8_t sAh[128 * ASTR], sAl[128 * ASTR];
    __shared__ __align__(16) uint8_t sBh[64 * ASTR],  sBl[64 * ASTR];

    const int tid = threadIdx.x, wid = tid >> 5, lane = tid & 31;
    const int wm = (wid & 3) * 32, wn = (wid >> 2) * 32;
    const int lrow = lane & 15, lch = lane >> 4;

    float acc[2][4][4] = {};
    float4 ra[4], rb[2];

#define GLOAD(c) do {                                                          \
    _Pragma("unroll")                                                          \
    for (int i = 0; i < 4; i++) {                                              \
        int slot = tid + i * 256; int row = slot >> 3, qq = slot & 7;          \
        ra[i] = *(const float4*)(A + (size_t)(bm + row) * CS + (c) * 32 + qq * 4); \
        if (A2) {                                                              \
            float4 t2 = *(const float4*)(A2 + (size_t)(bm + row) * CS + (c) * 32 + qq * 4); \
            ra[i].x *= t2.x; ra[i].y *= t2.y; ra[i].z *= t2.z; ra[i].w *= t2.w; \
        }                                                                      \
    }                                                                          \
    _Pragma("unroll")                                                          \
    for (int i = 0; i < 2; i++) {                                              \
        int slot = tid + i * 256; int row = slot >> 3, qq = slot & 7;          \
        rb[i] = *(const float4*)(Bw + (size_t)(bn + row) * CS + (c) * 32 + qq * 4); \
    } } while (0)

    GLOAD(0);
    for (int c = 0; c < 32; c++) {
        __syncthreads();
#pragma unroll
        for (int i = 0; i < 4; i++) {
            int slot = tid + i * 256; int row = slot >> 3, qq = slot & 7;
            uint2 hi, lo; split4(ra[i], &hi, &lo);
            *(uint2*)(sAh + row * ASTR + qq * 8) = hi;
            *(uint2*)(sAl + row * ASTR + qq * 8) = lo;
        }
#pragma unroll
        for (int i = 0; i < 2; i++) {
            int slot = tid + i * 256; int row = slot >> 3, qq = slot & 7;
            uint2 hi, lo; split4(rb[i], &hi, &lo);
            *(uint2*)(sBh + row * ASTR + qq * 8) = hi;
            *(uint2*)(sBl + row * ASTR + qq * 8) = lo;
        }
        __syncthreads();
        if (c < 31) GLOAD(c + 1);

#pragma unroll
        for (int kh = 0; kh < 2; kh++) {
            uint32_t Ah[2][4], Al[2][4], Bh[2][4], Bl[2][4];
#pragma unroll
            for (int mf = 0; mf < 2; mf++) {
                uint32_t off = (uint32_t)((wm + mf * 16 + lrow) * ASTR + kh * 32 + lch * 16);
                ldsm4(Ah[mf], smem_u32(sAh) + off);
                ldsm4(Al[mf], smem_u32(sAl) + off);
            }
#pragma unroll
            for (int gi = 0; gi < 2; gi++) {
                uint32_t off = (uint32_t)((wn + gi * 16 + lrow) * ASTR + kh * 32 + lch * 16);
                ldsm4(Bh[gi], smem_u32(sBh) + off);
                ldsm4(Bl[gi], smem_u32(sBl) + off);
            }
#pragma unroll
            for (int mf = 0; mf < 2; mf++)
#pragma unroll
                for (int nf = 0; nf < 4; nf++) {
                    int gi = nf >> 1, s2 = nf & 1;
                    mma_bf16(acc[mf][nf], Ah[mf], Bh[gi][s2], Bh[gi][s2 + 2]);
                    mma_bf16(acc[mf][nf], Ah[mf], Bl[gi][s2], Bl[gi][s2 + 2]);
                    mma_bf16(acc[mf][nf], Al[mf], Bh[gi][s2], Bh[gi][s2 + 2]);
                }
        }
    }
#undef GLOAD

#pragma unroll
    for (int mf = 0; mf < 2; mf++)
#pragma unroll
        for (int nf = 0; nf < 4; nf++) {
            int col = bn + wn + nf * 8 + (lane & 3) * 2;
#pragma unroll
            for (int rh = 0; rh < 2; rh++) {
                int row = bm + wm + mf * 16 + (lane >> 2) + rh * 8;
                float v0 = acc[mf][nf][rh * 2 + 0];
                float v1 = acc[mf][nf][rh * 2 + 1];
                if (mode == 1) { v0 += bias[col]; v1 += bias[col + 1]; }
                else if (mode == 2) {
                    v0 = 1.0f / (1.0f + __expf(-v0));
                    v1 = 1.0f / (1.0f + __expf(-v1));
                }
                float2 st; st.x = v0; st.y = v1;
                *(float2*)(C + (size_t)row * CS + col) = st;
            }
        }
}

__global__ __launch_bounds__(256) void mma_proj(
    const float* __restrict__ s, const float* __restrict__ k_in,
    const float* __restrict__ Wq, const float* __restrict__ bq,
    const float* __restrict__ Wk, const float* __restrict__ Wv,
    const float* __restrict__ Wg,
    float* __restrict__ q, float* __restrict__ k,
    float* __restrict__ v, float* __restrict__ g)
{
    const float* A; const float* B; const float* bias = nullptr;
    float* C; int mode = 0;
    switch (blockIdx.z) {
        case 0: A = s;    B = Wq; bias = bq; C = q; mode = 1; break;
        case 1: A = k_in; B = Wk;            C = k; break;
        case 2: A = k_in; B = Wv;            C = v; break;
        default: A = s;   B = Wg;            C = g; mode = 2; break;
    }
    gemm_mma_body(A, nullptr, B, bias, mode, C, blockIdx.y * 128, blockIdx.x * 64);
}

__global__ __launch_bounds__(256) void mma_gated(
    const float* __restrict__ o, const float* __restrict__ g,
    const float* __restrict__ Wo, float* __restrict__ out)
{
    gemm_mma_body(o, g, Wo, nullptr, 0, out, blockIdx.y * 128, blockIdx.x * 64);
}

// ============ z projection via mma: z[h][m] = bias[m,:].Wz[:,h] + mask =====
// Block: 128 threads / 4 warps, 128 m-rows, N=16 (all heads), K=128 in 4x32.
#define WSTR 272  // Wz^T smem row stride (128 bf16 = 256B + 16B pad)

__global__ __launch_bounds__(128) void z_mma(
    const float* __restrict__ bias, const float* __restrict__ Wz,
    const float* __restrict__ mask, float* __restrict__ z)
{
    __shared__ __align__(16) uint8_t sAh[128 * ASTR], sAl[128 * ASTR];
    __shared__ __align__(16) uint8_t sWh[16 * WSTR],  sWl[16 * WSTR];

    const int tid = threadIdx.x, wid = tid >> 5, lane = tid & 31;
    const size_t bm = (size_t)blockIdx.x * 128;
    const int wm = wid * 32;
    const int lrow = lane & 15, lch = lane >> 4;

    // Wz^T -> smem (hi/lo), rows = h, cols = c
#pragma unroll
    for (int i = 0; i < 16; i++) {
        int idx = tid + i * 128;
        int h = idx >> 7, c = idx & 127;
        float v = Wz[c * NH + h];
        __nv_bfloat16 hb = __float2bfloat16_rn(v);
        *(uint16_t*)(sWh + h * WSTR + c * 2) = __bfloat16_as_ushort(hb);
        *(uint16_t*)(sWl + h * WSTR + c * 2) =
            __bfloat16_as_ushort(__float2bfloat16_rn(v - __bfloat162float(hb)));
    }

    float acc[2][2][4] = {};
    float4 ra[8];

#define ZLOAD(c) do {                                                          \
    _Pragma("unroll")                                                          \
    for (int i = 0; i < 8; i++) {                                              \
        int slot = tid + i * 128; int row = slot >> 3, qq = slot & 7;          \
        ra[i] = *(const float4*)(bias + (bm + row) * CZ + (c) * 32 + qq * 4);  \
    } } while (0)

    ZLOAD(0);
    for (int c = 0; c < 4; c++) {
        __syncthreads();
#pragma unroll
        for (int i = 0; i < 8; i++) {
            int slot = tid + i * 128; int row = slot >> 3, qq = slot & 7;
            uint2 hi, lo; split4(ra[i], &hi, &lo);
            *(uint2*)(sAh + row * ASTR + qq * 8) = hi;
            *(uint2*)(sAl + row * ASTR + qq * 8) = lo;
        }
        __syncthreads();
        if (c < 3) ZLOAD(c + 1);

#pragma unroll
        for (int kh = 0; kh < 2; kh++) {
            uint32_t Wh[4], Wl[4];
            uint32_t woff = (uint32_t)(lrow * WSTR + c * 64 + kh * 32 + lch * 16);
            ldsm4(Wh, smem_u32(sWh) + woff);
            ldsm4(Wl, smem_u32(sWl) + woff);
#pragma unroll
            for (int mf = 0; mf < 2; mf++) {
                uint32_t Ah[4], Al[4];
                uint32_t off = (uint32_t)((wm + mf * 16 + lrow) * ASTR + kh * 32 + lch * 16);
                ldsm4(Ah, smem_u32(sAh) + off);
                ldsm4(Al, smem_u32(sAl) + off);
#pragma unroll
                for (int nf = 0; nf < 2; nf++) {
                    mma_bf16(acc[mf][nf], Ah, Wh[nf], Wh[nf + 2]);
                    mma_bf16(acc[mf][nf], Ah, Wl[nf], Wl[nf + 2]);
                    mma_bf16(acc[mf][nf], Al, Wh[nf], Wh[nf + 2]);
                }
            }
        }
    }
#undef ZLOAD

#pragma unroll
    for (int mf = 0; mf < 2; mf++)
#pragma unroll
        for (int rh = 0; rh < 2; rh++) {
            size_t m = bm + wm + mf * 16 + (lane >> 2) + rh * 8;
            float mterm = (1.0f - mask[m & (NJ - 1)]) * (-1000000.0f);
#pragma unroll
            for (int nf = 0; nf < 2; nf++) {
                int h0 = nf * 8 + (lane & 3) * 2;
                z[(size_t)h0 * ((size_t)NI * NJ) + m]       = acc[mf][nf][rh * 2 + 0] + mterm;
                z[(size_t)(h0 + 1) * ((size_t)NI * NJ) + m] = acc[mf][nf][rh * 2 + 1] + mterm;
            }
        }
}

// ---------------- attention: one block = (8 i-rows, 1 head) ----------------
__global__ __launch_bounds__(256) void attn_kernel(
    const float* __restrict__ q, const float* __restrict__ k,
    const float* __restrict__ v, const float* __restrict__ z,
    float* __restrict__ o)
{
    __shared__ float4 qs[8][16];
    __shared__ float  lg[8][1024];
    __shared__ float  inv_s[8];
    __shared__ float  part[4][8][64];

    const int tid = threadIdx.x;
    const int i0 = blockIdx.x * 8;
    const int h  = blockIdx.y;
    const float* zh = z + (size_t)h * ((size_t)NI * NJ);

    if (tid < 128) {
        int ii = tid >> 4, d4 = tid & 15;
        qs[ii][d4] = *(const float4*)(q + (size_t)(i0 + ii) * CS + h * ND + d4 * 4);
    }
    __syncthreads();

    for (int jj = 0; jj < 4; jj++) {
        int j = tid + jj * 256;
        float4 kr[16];
        const float4* kp = (const float4*)(k + (size_t)j * CS + h * ND);
#pragma unroll
        for (int d = 0; d < 16; d++) kr[d] = kp[d];
#pragma unroll
        for (int ii = 0; ii < 8; ii++) {
            float s = 0.f;
#pragma unroll
            for (int d = 0; d < 16; d++) {
                float4 a = qs[ii][d];
                s += a.x * kr[d].x + a.y * kr[d].y + a.z * kr[d].z + a.w * kr[d].w;
            }
            lg[ii][j] = s * 0.125f + zh[(size_t)(i0 + ii) * NJ + j];
        }
    }
    __syncthreads();

    {
        const int w = tid >> 5, lane = tid & 31;
        float mx = -1e30f;
        float4 vals[8];
#pragma unroll
        for (int kk = 0; kk < 8; kk++) {
            vals[kk] = *(const float4*)&lg[w][lane * 4 + kk * 128];
            mx = fmaxf(mx, fmaxf(fmaxf(vals[kk].x, vals[kk].y),
                                 fmaxf(vals[kk].z, vals[kk].w)));
        }
#pragma unroll
        for (int s = 16; s > 0; s >>= 1)
            mx = fmaxf(mx, __shfl_xor_sync(0xffffffffu, mx, s));
        float sum = 0.f;
#pragma unroll
        for (int kk = 0; kk < 8; kk++) {
            float4 e;
            e.x = __expf(vals[kk].x - mx);
            e.y = __expf(vals[kk].y - mx);
            e.z = __expf(vals[kk].z - mx);
            e.w = __expf(vals[kk].w - mx);
            sum += e.x + e.y + e.z + e.w;
            *(float4*)&lg[w][lane * 4 + kk * 128] = e;
        }
#pragma unroll
        for (int s = 16; s > 0; s >>= 1)
            sum += __shfl_xor_sync(0xffffffffu, sum, s);
        if (lane == 0) inv_s[w] = 1.0f / sum;
    }
    __syncthreads();

    {
        const int d = tid & 63, qt = tid >> 6;
        float acc[8] = {};
        const float* vp = v + h * ND + d;
        for (int j4 = qt * 64; j4 < qt * 64 + 64; j4++) {
            int j = j4 * 4;
            float v0 = vp[(size_t)(j + 0) * CS];
            float v1 = vp[(size_t)(j + 1) * CS];
            float v2 = vp[(size_t)(j + 2) * CS];
            float v3 = vp[(size_t)(j + 3) * CS];
#pragma unroll
            for (int ii = 0; ii < 8; ii++) {
                float4 p = *(const float4*)&lg[ii][j];
                acc[ii] += p.x * v0 + p.y * v1 + p.z * v2 + p.w * v3;
            }
        }
#pragma unroll
        for (int ii = 0; ii < 8; ii++) part[qt][ii][d] = acc[ii];
    }
    __syncthreads();

    for (int lin = tid; lin < 512; lin += 256) {
        int ii = lin >> 6, dd = lin & 63;
        float s = part[0][ii][dd] + part[1][ii][dd] +
                  part[2][ii][dd] + part[3][ii][dd];
        o[(size_t)(i0 + ii) * CS + h * ND + dd] = s * inv_s[ii];
    }
}

// ---------------------------------------------------------------------------
extern "C" void kernel_launch(void* const* d_in, const int* in_sizes, int n_in,
                              void* d_out, int out_size)
{
    (void)in_sizes; (void)n_in; (void)out_size;
    const float* s    = (const float*)d_in[0];
    const float* k_in = (const float*)d_in[1];
    const float* mask = (const float*)d_in[2];
    const float* bias = (const float*)d_in[3];
    const float* Wq   = (const float*)d_in[4];
    const float* bq   = (const float*)d_in[5];
    const float* Wk   = (const float*)d_in[6];
    const float* Wv   = (const float*)d_in[7];
    const float* Wg   = (const float*)d_in[8];
    const float* Wo   = (const float*)d_in[9];
    const float* Wz   = (const float*)d_in[10];
    float* out = (float*)d_out;

    float *q, *k, *v, *g, *o, *z;
    cudaGetSymbolAddress((void**)&q, g_q);
    cudaGetSymbolAddress((void**)&k, g_k);
    cudaGetSymbolAddress((void**)&v, g_v);
    cudaGetSymbolAddress((void**)&g, g_gt);
    cudaGetSymbolAddress((void**)&o, g_o);
    cudaGetSymbolAddress((void**)&z, g_z);

    // 4 projections on mma.sync tensor cores (one launch)
    mma_proj<<<dim3(16, 8, 4), 256>>>(s, k_in, Wq, bq, Wk, Wv, Wg, q, k, v, g);
    // pair-bias projection + mask on mma.sync
    z_mma<<<(NI * NJ) / 128, 128>>>(bias, Wz, mask, z);
    // attention (fp32 SIMT, unchanged this round)
    attn_kernel<<<dim3(NI / 8, NH), 256>>>(q, k, v, z, o);
    // gated output projection on mma.sync
    mma_gated<<<dim3(16, 8), 256>>>(o, g, Wo, out);
}

// round 8
// speedup vs baseline: 3.7632x; 1.9605x over previous
#include <cuda_runtime.h>
#include <cuda_bf16.h>
#include <stdint.h>
#include <math.h>

#define CS 1024
#define NI 1024
#define NJ 1024
#define NH 16
#define ND 64
#define CZ 128

// ---------------- scratch (device globals; no allocation allowed) ----------
__device__ float g_q[NI * CS];
__device__ float g_k[NJ * CS];
__device__ float g_v[NJ * CS];
__device__ float g_gt[NI * CS];
__device__ float g_o[NI * CS];
__device__ float g_z[(size_t)NH * NI * NJ];   // layout [h][i*NJ + j], 64 MB

// ===================== mma.sync helpers (sm_80+ PTX, no 'a' gate) ==========
__device__ __forceinline__ uint32_t smem_u32(const void* p) {
    uint32_t r;
    asm("{ .reg .u64 t; cvta.to.shared.u64 t, %1; cvt.u32.u64 %0, t; }"
        : "=r"(r) : "l"(p));
    return r;
}
__device__ __forceinline__ void ldsm4(uint32_t* r, uint32_t a) {
    asm volatile("ldmatrix.sync.aligned.m8n8.x4.shared.b16 {%0,%1,%2,%3}, [%4];"
                 : "=r"(r[0]), "=r"(r[1]), "=r"(r[2]), "=r"(r[3]) : "r"(a));
}
__device__ __forceinline__ void ldsm4t(uint32_t* r, uint32_t a) {
    asm volatile("ldmatrix.sync.aligned.m8n8.x4.trans.shared.b16 {%0,%1,%2,%3}, [%4];"
                 : "=r"(r[0]), "=r"(r[1]), "=r"(r[2]), "=r"(r[3]) : "r"(a));
}
__device__ __forceinline__ void mma_bf16(float* d, const uint32_t* a,
                                         uint32_t b0, uint32_t b1) {
    asm volatile(
        "mma.sync.aligned.m16n8k16.row.col.f32.bf16.bf16.f32 "
        "{%0,%1,%2,%3}, {%4,%5,%6,%7}, {%8,%9}, {%0,%1,%2,%3};"
        : "+f"(d[0]), "+f"(d[1]), "+f"(d[2]), "+f"(d[3])
        : "r"(a[0]), "r"(a[1]), "r"(a[2]), "r"(a[3]), "r"(b0), "r"(b1));
}
__device__ __forceinline__ uint32_t pack2(__nv_bfloat16 a, __nv_bfloat16 b) {
    return (uint32_t)__bfloat16_as_ushort(a) |
           ((uint32_t)__bfloat16_as_ushort(b) << 16);
}
// fp32x4 -> bf16 hi (8B) + bf16 lo residual (8B)
__device__ __forceinline__ void split4(float4 v, uint2* hi, uint2* lo) {
    __nv_bfloat16 h0 = __float2bfloat16_rn(v.x);
    __nv_bfloat16 h1 = __float2bfloat16_rn(v.y);
    __nv_bfloat16 h2 = __float2bfloat16_rn(v.z);
    __nv_bfloat16 h3 = __float2bfloat16_rn(v.w);
    hi->x = pack2(h0, h1); hi->y = pack2(h2, h3);
    lo->x = pack2(__float2bfloat16_rn(v.x - __bfloat162float(h0)),
                  __float2bfloat16_rn(v.y - __bfloat162float(h1)));
    lo->y = pack2(__float2bfloat16_rn(v.z - __bfloat162float(h2)),
                  __float2bfloat16_rn(v.w - __bfloat162float(h3)));
}

// ============ bf16-split mma GEMM: C[128,64] tile of A[M,K]*B[N,K]^T =======
#define ASTR 80   // smem row stride bytes (32 bf16 = 64B data + 16B pad)

__device__ __forceinline__ void gemm_mma_body(
    const float* __restrict__ A, const float* __restrict__ A2,
    const float* __restrict__ Bw, const float* __restrict__ bias, int mode,
    float* __restrict__ C, int bm, int bn)
{
    __shared__ __align__(16) uint8_t sAh[128 * ASTR], sAl[128 * ASTR];
    __shared__ __align__(16) uint8_t sBh[64 * ASTR],  sBl[64 * ASTR];

    const int tid = threadIdx.x, wid = tid >> 5, lane = tid & 31;
    const int wm = (wid & 3) * 32, wn = (wid >> 2) * 32;
    const int lrow = lane & 15, lch = lane >> 4;

    float acc[2][4][4] = {};
    float4 ra[4], rb[2];

#define GLOAD(c) do {                                                          \
    _Pragma("unroll")                                                          \
    for (int i = 0; i < 4; i++) {                                              \
        int slot = tid + i * 256; int row = slot >> 3, qq = slot & 7;          \
        ra[i] = *(const float4*)(A + (size_t)(bm + row) * CS + (c) * 32 + qq * 4); \
        if (A2) {                                                              \
            float4 t2 = *(const float4*)(A2 + (size_t)(bm + row) * CS + (c) * 32 + qq * 4); \
            ra[i].x *= t2.x; ra[i].y *= t2.y; ra[i].z *= t2.z; ra[i].w *= t2.w; \
        }                                                                      \
    }                                                                          \
    _Pragma("unroll")                                                          \
    for (int i = 0; i < 2; i++) {                                              \
        int slot = tid + i * 256; int row = slot >> 3, qq = slot & 7;          \
        rb[i] = *(const float4*)(Bw + (size_t)(bn + row) * CS + (c) * 32 + qq * 4); \
    } } while (0)

    GLOAD(0);
    for (int c = 0; c < 32; c++) {
        __syncthreads();
#pragma unroll
        for (int i = 0; i < 4; i++) {
            int slot = tid + i * 256; int row = slot >> 3, qq = slot & 7;
            uint2 hi, lo; split4(ra[i], &hi, &lo);
            *(uint2*)(sAh + row * ASTR + qq * 8) = hi;
            *(uint2*)(sAl + row * ASTR + qq * 8) = lo;
        }
#pragma unroll
        for (int i = 0; i < 2; i++) {
            int slot = tid + i * 256; int row = slot >> 3, qq = slot & 7;
            uint2 hi, lo; split4(rb[i], &hi, &lo);
            *(uint2*)(sBh + row * ASTR + qq * 8) = hi;
            *(uint2*)(sBl + row * ASTR + qq * 8) = lo;
        }
        __syncthreads();
        if (c < 31) GLOAD(c + 1);

#pragma unroll
        for (int kh = 0; kh < 2; kh++) {
            uint32_t Ah[2][4], Al[2][4], Bh[2][4], Bl[2][4];
#pragma unroll
            for (int mf = 0; mf < 2; mf++) {
                uint32_t off = (uint32_t)((wm + mf * 16 + lrow) * ASTR + kh * 32 + lch * 16);
                ldsm4(Ah[mf], smem_u32(sAh) + off);
                ldsm4(Al[mf], smem_u32(sAl) + off);
            }
#pragma unroll
            for (int gi = 0; gi < 2; gi++) {
                uint32_t off = (uint32_t)((wn + gi * 16 + lrow) * ASTR + kh * 32 + lch * 16);
                ldsm4(Bh[gi], smem_u32(sBh) + off);
                ldsm4(Bl[gi], smem_u32(sBl) + off);
            }
#pragma unroll
            for (int mf = 0; mf < 2; mf++)
#pragma unroll
                for (int nf = 0; nf < 4; nf++) {
                    int gi = nf >> 1, s2 = nf & 1;
                    mma_bf16(acc[mf][nf], Ah[mf], Bh[gi][s2], Bh[gi][s2 + 2]);
                    mma_bf16(acc[mf][nf], Ah[mf], Bl[gi][s2], Bl[gi][s2 + 2]);
                    mma_bf16(acc[mf][nf], Al[mf], Bh[gi][s2], Bh[gi][s2 + 2]);
                }
        }
    }
#undef GLOAD

#pragma unroll
    for (int mf = 0; mf < 2; mf++)
#pragma unroll
        for (int nf = 0; nf < 4; nf++) {
            int col = bn + wn + nf * 8 + (lane & 3) * 2;
#pragma unroll
            for (int rh = 0; rh < 2; rh++) {
                int row = bm + wm + mf * 16 + (lane >> 2) + rh * 8;
                float v0 = acc[mf][nf][rh * 2 + 0];
                float v1 = acc[mf][nf][rh * 2 + 1];
                if (mode == 1) { v0 += bias[col]; v1 += bias[col + 1]; }
                else if (mode == 2) {
                    v0 = 1.0f / (1.0f + __expf(-v0));
                    v1 = 1.0f / (1.0f + __expf(-v1));
                }
                float2 st; st.x = v0; st.y = v1;
                *(float2*)(C + (size_t)row * CS + col) = st;
            }
        }
}

__global__ __launch_bounds__(256) void mma_proj(
    const float* __restrict__ s, const float* __restrict__ k_in,
    const float* __restrict__ Wq, const float* __restrict__ bq,
    const float* __restrict__ Wk, const float* __restrict__ Wv,
    const float* __restrict__ Wg,
    float* __restrict__ q, float* __restrict__ k,
    float* __restrict__ v, float* __restrict__ g)
{
    const float* A; const float* B; const float* bias = nullptr;
    float* C; int mode = 0;
    switch (blockIdx.z) {
        case 0: A = s;    B = Wq; bias = bq; C = q; mode = 1; break;
        case 1: A = k_in; B = Wk;            C = k; break;
        case 2: A = k_in; B = Wv;            C = v; break;
        default: A = s;   B = Wg;            C = g; mode = 2; break;
    }
    gemm_mma_body(A, nullptr, B, bias, mode, C, blockIdx.y * 128, blockIdx.x * 64);
}

__global__ __launch_bounds__(256) void mma_gated(
    const float* __restrict__ o, const float* __restrict__ g,
    const float* __restrict__ Wo, float* __restrict__ out)
{
    gemm_mma_body(o, g, Wo, nullptr, 0, out, blockIdx.y * 128, blockIdx.x * 64);
}

// ============ z projection via mma: z[h][m] = bias[m,:].Wz[:,h] + mask =====
#define WSTR 272  // Wz^T smem row stride (128 bf16 = 256B + 16B pad)

__global__ __launch_bounds__(128) void z_mma(
    const float* __restrict__ bias, const float* __restrict__ Wz,
    const float* __restrict__ mask, float* __restrict__ z)
{
    __shared__ __align__(16) uint8_t sAh[128 * ASTR], sAl[128 * ASTR];
    __shared__ __align__(16) uint8_t sWh[16 * WSTR],  sWl[16 * WSTR];

    const int tid = threadIdx.x, wid = tid >> 5, lane = tid & 31;
    const size_t bm = (size_t)blockIdx.x * 128;
    const int wm = wid * 32;
    const int lrow = lane & 15, lch = lane >> 4;

#pragma unroll
    for (int i = 0; i < 16; i++) {
        int idx = tid + i * 128;
        int h = idx >> 7, c = idx & 127;
        float v = Wz[c * NH + h];
        __nv_bfloat16 hb = __float2bfloat16_rn(v);
        *(uint16_t*)(sWh + h * WSTR + c * 2) = __bfloat16_as_ushort(hb);
        *(uint16_t*)(sWl + h * WSTR + c * 2) =
            __bfloat16_as_ushort(__float2bfloat16_rn(v - __bfloat162float(hb)));
    }

    float acc[2][2][4] = {};
    float4 ra[8];

#define ZLOAD(c) do {                                                          \
    _Pragma("unroll")                                                          \
    for (int i = 0; i < 8; i++) {                                              \
        int slot = tid + i * 128; int row = slot >> 3, qq = slot & 7;          \
        ra[i] = *(const float4*)(bias + (bm + row) * CZ + (c) * 32 + qq * 4);  \
    } } while (0)

    ZLOAD(0);
    for (int c = 0; c < 4; c++) {
        __syncthreads();
#pragma unroll
        for (int i = 0; i < 8; i++) {
            int slot = tid + i * 128; int row = slot >> 3, qq = slot & 7;
            uint2 hi, lo; split4(ra[i], &hi, &lo);
            *(uint2*)(sAh + row * ASTR + qq * 8) = hi;
            *(uint2*)(sAl + row * ASTR + qq * 8) = lo;
        }
        __syncthreads();
        if (c < 3) ZLOAD(c + 1);

#pragma unroll
        for (int kh = 0; kh < 2; kh++) {
            uint32_t Wh[4], Wl[4];
            uint32_t woff = (uint32_t)(lrow * WSTR + c * 64 + kh * 32 + lch * 16);
            ldsm4(Wh, smem_u32(sWh) + woff);
            ldsm4(Wl, smem_u32(sWl) + woff);
#pragma unroll
            for (int mf = 0; mf < 2; mf++) {
                uint32_t Ah[4], Al[4];
                uint32_t off = (uint32_t)((wm + mf * 16 + lrow) * ASTR + kh * 32 + lch * 16);
                ldsm4(Ah, smem_u32(sAh) + off);
                ldsm4(Al, smem_u32(sAl) + off);
#pragma unroll
                for (int nf = 0; nf < 2; nf++) {
                    mma_bf16(acc[mf][nf], Ah, Wh[nf], Wh[nf + 2]);
                    mma_bf16(acc[mf][nf], Ah, Wl[nf], Wl[nf + 2]);
                    mma_bf16(acc[mf][nf], Al, Wh[nf], Wh[nf + 2]);
                }
            }
        }
    }
#undef ZLOAD

#pragma unroll
    for (int mf = 0; mf < 2; mf++)
#pragma unroll
        for (int rh = 0; rh < 2; rh++) {
            size_t m = bm + wm + mf * 16 + (lane >> 2) + rh * 8;
            float mterm = (1.0f - mask[m & (NJ - 1)]) * (-1000000.0f);
#pragma unroll
            for (int nf = 0; nf < 2; nf++) {
                int h0 = nf * 8 + (lane & 3) * 2;
                z[(size_t)h0 * ((size_t)NI * NJ) + m]       = acc[mf][nf][rh * 2 + 0] + mterm;
                z[(size_t)(h0 + 1) * ((size_t)NI * NJ) + m] = acc[mf][nf][rh * 2 + 1] + mterm;
            }
        }
}

// ============ attention on mma.sync: block = 32 i-rows x 1 head ============
// Pass A: S = (Q K^T)*0.125 -> smem logits (bf16-split, fp32 acc)
// Pass B: row softmax with z added in-pass (fp32, exact)
// Pass C: O = P V (P and V bf16-split), fp32 acc in registers
#define FSTR 144                 // bf16 tile row stride: 64 bf16 = 128B + 16B pad
#define LGW 1032                 // logit row stride in floats
#define OFF_LG 0
#define OFF_QH 132096
#define OFF_QL (OFF_QH + 32 * FSTR)
#define OFF_KH (OFF_QL + 32 * FSTR)
#define OFF_KL (OFF_KH + 64 * FSTR)
#define OFF_PH (OFF_KL + 64 * FSTR)
#define OFF_PL (OFF_PH + 32 * FSTR)
#define OFF_INV (OFF_PL + 32 * FSTR)
#define ATTN_SMEM (OFF_INV + 128)

__global__ __launch_bounds__(256) void attn_mma(
    const float* __restrict__ q, const float* __restrict__ k,
    const float* __restrict__ v, const float* __restrict__ z,
    float* __restrict__ o)
{
    extern __shared__ __align__(16) uint8_t dsm[];
    float* lg = (float*)(dsm + OFF_LG);
    float* invs = (float*)(dsm + OFF_INV);
    const uint32_t sb = smem_u32(dsm);

    const int tid = threadIdx.x, wid = tid >> 5, lane = tid & 31;
    const int i0 = blockIdx.x * 32;
    const int h  = blockIdx.y;
    const int wm = (wid & 1) * 16;       // warp i-rows
    const int wn = (wid >> 1) * 16;      // warp n (j in pass A, d in pass C)
    const int lrow = lane & 15, lch = lane >> 4;
    const float* zh = z + (size_t)h * ((size_t)NI * NJ);

    // load Q tile (32 x 64) split hi/lo
#pragma unroll
    for (int i = 0; i < 2; i++) {
        int slot = tid + i * 256; int row = slot >> 4, q4 = slot & 15;
        float4 t = *(const float4*)(q + (size_t)(i0 + row) * CS + h * ND + q4 * 4);
        uint2 hi, lo; split4(t, &hi, &lo);
        *(uint2*)(dsm + OFF_QH + row * FSTR + q4 * 8) = hi;
        *(uint2*)(dsm + OFF_QL + row * FSTR + q4 * 8) = lo;
    }

    // ---------------- Pass A: logits ----------------
    for (int c = 0; c < 16; c++) {
        __syncthreads();
#pragma unroll
        for (int i = 0; i < 4; i++) {
            int slot = tid + i * 256; int row = slot >> 4, q4 = slot & 15;
            float4 t = *(const float4*)(k + (size_t)(c * 64 + row) * CS + h * ND + q4 * 4);
            uint2 hi, lo; split4(t, &hi, &lo);
            *(uint2*)(dsm + OFF_KH + row * FSTR + q4 * 8) = hi;
            *(uint2*)(dsm + OFF_KL + row * FSTR + q4 * 8) = lo;
        }
        __syncthreads();

        float accS[2][4] = {};
#pragma unroll
        for (int kh = 0; kh < 4; kh++) {
            uint32_t Ah[4], Al[4], Bh[4], Bl[4];
            uint32_t aoff = (uint32_t)((wm + lrow) * FSTR + kh * 32 + lch * 16);
            ldsm4(Ah, sb + OFF_QH + aoff);
            ldsm4(Al, sb + OFF_QL + aoff);
            uint32_t boff = (uint32_t)((wn + lrow) * FSTR + kh * 32 + lch * 16);
            ldsm4(Bh, sb + OFF_KH + boff);
            ldsm4(Bl, sb + OFF_KL + boff);
#pragma unroll
            for (int nf = 0; nf < 2; nf++) {
                mma_bf16(accS[nf], Ah, Bh[nf], Bh[nf + 2]);
                mma_bf16(accS[nf], Ah, Bl[nf], Bl[nf + 2]);
                mma_bf16(accS[nf], Al, Bh[nf], Bh[nf + 2]);
            }
        }
#pragma unroll
        for (int nf = 0; nf < 2; nf++) {
            int col = c * 64 + wn + nf * 8 + (lane & 3) * 2;
            int r0 = wm + (lane >> 2);
            float2 s0; s0.x = accS[nf][0] * 0.125f; s0.y = accS[nf][1] * 0.125f;
            float2 s1; s1.x = accS[nf][2] * 0.125f; s1.y = accS[nf][3] * 0.125f;
            *(float2*)&lg[(size_t)r0 * LGW + col] = s0;
            *(float2*)&lg[(size_t)(r0 + 8) * LGW + col] = s1;
        }
    }
    __syncthreads();

    // ---------------- Pass B: softmax (z added here) ----------------
#pragma unroll
    for (int t = 0; t < 4; t++) {
        int r = wid * 4 + t;
        const float* zr = zh + (size_t)(i0 + r) * NJ;
        float4 vals[8];
        float mx = -1e30f;
#pragma unroll
        for (int kk = 0; kk < 8; kk++) {
            int j = lane * 4 + kk * 128;
            float4 a = *(const float4*)&lg[(size_t)r * LGW + j];
            float4 zb = *(const float4*)&zr[j];
            a.x += zb.x; a.y += zb.y; a.z += zb.z; a.w += zb.w;
            vals[kk] = a;
            mx = fmaxf(mx, fmaxf(fmaxf(a.x, a.y), fmaxf(a.z, a.w)));
        }
#pragma unroll
        for (int s = 16; s > 0; s >>= 1)
            mx = fmaxf(mx, __shfl_xor_sync(0xffffffffu, mx, s));
        float sum = 0.f;
#pragma unroll
        for (int kk = 0; kk < 8; kk++) {
            int j = lane * 4 + kk * 128;
            float4 e;
            e.x = __expf(vals[kk].x - mx);
            e.y = __expf(vals[kk].y - mx);
            e.z = __expf(vals[kk].z - mx);
            e.w = __expf(vals[kk].w - mx);
            sum += e.x + e.y + e.z + e.w;
            *(float4*)&lg[(size_t)r * LGW + j] = e;
        }
#pragma unroll
        for (int s = 16; s > 0; s >>= 1)
            sum += __shfl_xor_sync(0xffffffffu, sum, s);
        if (lane == 0) invs[r] = 1.0f / sum;
    }

    // ---------------- Pass C: O = P V ----------------
    float accO[2][4] = {};
    for (int c = 0; c < 16; c++) {
        __syncthreads();
        // V chunk (64 j x 64 d) split
#pragma unroll
        for (int i = 0; i < 4; i++) {
            int slot = tid + i * 256; int row = slot >> 4, q4 = slot & 15;
            float4 t = *(const float4*)(v + (size_t)(c * 64 + row) * CS + h * ND + q4 * 4);
            uint2 hi, lo; split4(t, &hi, &lo);
            *(uint2*)(dsm + OFF_KH + row * FSTR + q4 * 8) = hi;
            *(uint2*)(dsm + OFF_KL + row * FSTR + q4 * 8) = lo;
        }
        // P chunk (32 i x 64 j) split from logits smem
#pragma unroll
        for (int i = 0; i < 2; i++) {
            int slot = tid + i * 256; int row = slot >> 4, q4 = slot & 15;
            float4 t = *(const float4*)&lg[(size_t)row * LGW + c * 64 + q4 * 4];
            uint2 hi, lo; split4(t, &hi, &lo);
            *(uint2*)(dsm + OFF_PH + row * FSTR + q4 * 8) = hi;
            *(uint2*)(dsm + OFF_PL + row * FSTR + q4 * 8) = lo;
        }
        __syncthreads();

#pragma unroll
        for (int kh = 0; kh < 4; kh++) {
            uint32_t Ph[4], Pl[4], Vh[4], Vl[4];
            uint32_t aoff = (uint32_t)((wm + lrow) * FSTR + kh * 32 + lch * 16);
            ldsm4(Ph, sb + OFF_PH + aoff);
            ldsm4(Pl, sb + OFF_PL + aoff);
            // V as B-operand via transposed ldmatrix: rows = j (k-dim), cols = d
            uint32_t voff = (uint32_t)((kh * 16 + lrow) * FSTR + wn * 2 + lch * 16);
            ldsm4t(Vh, sb + OFF_KH + voff);
            ldsm4t(Vl, sb + OFF_KL + voff);
#pragma unroll
            for (int nf = 0; nf < 2; nf++) {
                mma_bf16(accO[nf], Ph, Vh[nf * 2], Vh[nf * 2 + 1]);
                mma_bf16(accO[nf], Ph, Vl[nf * 2], Vl[nf * 2 + 1]);
                mma_bf16(accO[nf], Pl, Vh[nf * 2], Vh[nf * 2 + 1]);
            }
        }
    }
    __syncthreads();

    // epilogue: scale by 1/sum and store
#pragma unroll
    for (int nf = 0; nf < 2; nf++) {
        int col = h * ND + wn + nf * 8 + (lane & 3) * 2;
#pragma unroll
        for (int rh = 0; rh < 2; rh++) {
            int r = wm + (lane >> 2) + rh * 8;
            float is = invs[r];
            float2 st;
            st.x = accO[nf][rh * 2 + 0] * is;
            st.y = accO[nf][rh * 2 + 1] * is;
            *(float2*)(o + (size_t)(i0 + r) * CS + col) = st;
        }
    }
}

// ---------------------------------------------------------------------------
extern "C" void kernel_launch(void* const* d_in, const int* in_sizes, int n_in,
                              void* d_out, int out_size)
{
    (void)in_sizes; (void)n_in; (void)out_size;
    const float* s    = (const float*)d_in[0];
    const float* k_in = (const float*)d_in[1];
    const float* mask = (const float*)d_in[2];
    const float* bias = (const float*)d_in[3];
    const float* Wq   = (const float*)d_in[4];
    const float* bq   = (const float*)d_in[5];
    const float* Wk   = (const float*)d_in[6];
    const float* Wv   = (const float*)d_in[7];
    const float* Wg   = (const float*)d_in[8];
    const float* Wo   = (const float*)d_in[9];
    const float* Wz   = (const float*)d_in[10];
    float* out = (float*)d_out;

    float *q, *k, *v, *g, *o, *z;
    cudaGetSymbolAddress((void**)&q, g_q);
    cudaGetSymbolAddress((void**)&k, g_k);
    cudaGetSymbolAddress((void**)&v, g_v);
    cudaGetSymbolAddress((void**)&g, g_gt);
    cudaGetSymbolAddress((void**)&o, g_o);
    cudaGetSymbolAddress((void**)&z, g_z);

    cudaFuncSetAttribute(attn_mma, cudaFuncAttributeMaxDynamicSharedMemorySize,
                         ATTN_SMEM);

    // 4 projections on mma.sync tensor cores (one launch)
    mma_proj<<<dim3(16, 8, 4), 256>>>(s, k_in, Wq, bq, Wk, Wv, Wg, q, k, v, g);
    // pair-bias projection + mask on mma.sync
    z_mma<<<(NI * NJ) / 128, 128>>>(bias, Wz, mask, z);
    // attention on mma.sync (bf16-split QK^T and PV)
    attn_mma<<<dim3(NI / 32, NH), 256, ATTN_SMEM>>>(q, k, v, z, o);
    // gated output projection on mma.sync
    mma_gated<<<dim3(16, 8), 256>>>(o, g, Wo, out);
}

// round 9
// speedup vs baseline: 3.9394x; 1.0468x over previous
#include <cuda_runtime.h>
#include <cuda_bf16.h>
#include <stdint.h>
#include <math.h>

#define CS 1024
#define NI 1024
#define NJ 1024
#define NH 16
#define ND 64
#define CZ 128

// ---------------- scratch (device globals; no allocation allowed) ----------
__device__ float g_gt[NI * CS];                       // sigmoid gate (fp32)
__device__ float g_z[(size_t)NH * NI * NJ];           // pair bias [h][i*NJ+j]
// bf16 hi/lo split copies
__device__ __nv_bfloat16 g_sh[NI * CS],  g_sl[NI * CS];
__device__ __nv_bfloat16 g_kih[NJ * CS], g_kil[NJ * CS];
__device__ __nv_bfloat16 g_Wqh[CS * CS], g_Wql[CS * CS];
__device__ __nv_bfloat16 g_Wkh[CS * CS], g_Wkl[CS * CS];
__device__ __nv_bfloat16 g_Wvh[CS * CS], g_Wvl[CS * CS];
__device__ __nv_bfloat16 g_Wgh[CS * CS], g_Wgl[CS * CS];
__device__ __nv_bfloat16 g_Woh[CS * CS], g_Wol[CS * CS];
__device__ __nv_bfloat16 g_qh[NI * CS],  g_ql[NI * CS];
__device__ __nv_bfloat16 g_kh[NJ * CS],  g_kl[NJ * CS];
__device__ __nv_bfloat16 g_vh[NJ * CS],  g_vl[NJ * CS];
__device__ __nv_bfloat16 g_goh[NI * CS], g_gol[NI * CS];

// ===================== mma.sync / cp.async helpers =========================
__device__ __forceinline__ uint32_t smem_u32(const void* p) {
    uint32_t r;
    asm("{ .reg .u64 t; cvta.to.shared.u64 t, %1; cvt.u32.u64 %0, t; }"
        : "=r"(r) : "l"(p));
    return r;
}
__device__ __forceinline__ void ldsm4(uint32_t* r, uint32_t a) {
    asm volatile("ldmatrix.sync.aligned.m8n8.x4.shared.b16 {%0,%1,%2,%3}, [%4];"
                 : "=r"(r[0]), "=r"(r[1]), "=r"(r[2]), "=r"(r[3]) : "r"(a));
}
__device__ __forceinline__ void ldsm4t(uint32_t* r, uint32_t a) {
    asm volatile("ldmatrix.sync.aligned.m8n8.x4.trans.shared.b16 {%0,%1,%2,%3}, [%4];"
                 : "=r"(r[0]), "=r"(r[1]), "=r"(r[2]), "=r"(r[3]) : "r"(a));
}
__device__ __forceinline__ void mma_bf16(float* d, const uint32_t* a,
                                         uint32_t b0, uint32_t b1) {
    asm volatile(
        "mma.sync.aligned.m16n8k16.row.col.f32.bf16.bf16.f32 "
        "{%0,%1,%2,%3}, {%4,%5,%6,%7}, {%8,%9}, {%0,%1,%2,%3};"
        : "+f"(d[0]), "+f"(d[1]), "+f"(d[2]), "+f"(d[3])
        : "r"(a[0]), "r"(a[1]), "r"(a[2]), "r"(a[3]), "r"(b0), "r"(b1));
}
__device__ __forceinline__ void cpa16(uint32_t s, const void* g) {
    asm volatile("cp.async.cg.shared.global [%0], [%1], 16;" :: "r"(s), "l"(g));
}
__device__ __forceinline__ void cpa_commit() {
    asm volatile("cp.async.commit_group;");
}
template <int N> __device__ __forceinline__ void cpa_wait() {
    asm volatile("cp.async.wait_group %0;" :: "n"(N));
}
__device__ __forceinline__ uint32_t pack2(__nv_bfloat16 a, __nv_bfloat16 b) {
    return (uint32_t)__bfloat16_as_ushort(a) |
           ((uint32_t)__bfloat16_as_ushort(b) << 16);
}
__device__ __forceinline__ void split4(float4 v, uint2* hi, uint2* lo) {
    __nv_bfloat16 h0 = __float2bfloat16_rn(v.x);
    __nv_bfloat16 h1 = __float2bfloat16_rn(v.y);
    __nv_bfloat16 h2 = __float2bfloat16_rn(v.z);
    __nv_bfloat16 h3 = __float2bfloat16_rn(v.w);
    hi->x = pack2(h0, h1); hi->y = pack2(h2, h3);
    lo->x = pack2(__float2bfloat16_rn(v.x - __bfloat162float(h0)),
                  __float2bfloat16_rn(v.y - __bfloat162float(h1)));
    lo->y = pack2(__float2bfloat16_rn(v.z - __bfloat162float(h2)),
                  __float2bfloat16_rn(v.w - __bfloat162float(h3)));
}
__device__ __forceinline__ void split2(float v0, float v1,
                                       uint32_t* hp, uint32_t* lp) {
    __nv_bfloat16 h0 = __float2bfloat16_rn(v0);
    __nv_bfloat16 h1 = __float2bfloat16_rn(v1);
    *hp = pack2(h0, h1);
    *lp = pack2(__float2bfloat16_rn(v0 - __bfloat162float(h0)),
                __float2bfloat16_rn(v1 - __bfloat162float(h1)));
}

// ============ preconvert: fp32 -> bf16 hi/lo for 7 matrices (1M each) ======
__global__ __launch_bounds__(256) void preconv(
    const float* __restrict__ s, const float* __restrict__ kin,
    const float* __restrict__ Wq, const float* __restrict__ Wk,
    const float* __restrict__ Wv, const float* __restrict__ Wg,
    const float* __restrict__ Wo)
{
    const float* src; __nv_bfloat16 *dh, *dl;
    switch (blockIdx.y) {
        case 0: src = s;   dh = g_sh;  dl = g_sl;  break;
        case 1: src = kin; dh = g_kih; dl = g_kil; break;
        case 2: src = Wq;  dh = g_Wqh; dl = g_Wql; break;
        case 3: src = Wk;  dh = g_Wkh; dl = g_Wkl; break;
        case 4: src = Wv;  dh = g_Wvh; dl = g_Wvl; break;
        case 5: src = Wg;  dh = g_Wgh; dl = g_Wgl; break;
        default: src = Wo; dh = g_Woh; dl = g_Wol; break;
    }
    const int stride = gridDim.x * 256;
    for (int i = blockIdx.x * 256 + threadIdx.x; i < (CS * CS) / 4; i += stride) {
        float4 v = ((const float4*)src)[i];
        uint2 hi, lo; split4(v, &hi, &lo);
        ((uint2*)dh)[i] = hi;
        ((uint2*)dl)[i] = lo;
    }
}

// ====== bf16-split GEMM v2: cp.async 2-stage, pure-bf16 main loop ==========
// C[128,64] tile of A[M,K]*B[N,K]^T. 256 threads, 8 warps (4m x 2n).
#define ASTR 80
#define SA_BYTES (128 * ASTR)
#define SB_BYTES (64 * ASTR)
#define STAGE_B (2 * SA_BYTES + 2 * SB_BYTES)   // 30720
#define GEMM_SMEM (2 * STAGE_B)

// epilogue modes
#define EP_F32 0
#define EP_PAIR 1
#define EP_PAIR_BIAS 2
#define EP_F32_SIG 3

__device__ __forceinline__ void gemm_bf16_body(
    const __nv_bfloat16* __restrict__ Ah, const __nv_bfloat16* __restrict__ Al,
    const __nv_bfloat16* __restrict__ Bh, const __nv_bfloat16* __restrict__ Bl,
    const float* __restrict__ bias, int mode,
    float* __restrict__ Cf, __nv_bfloat16* __restrict__ Ch,
    __nv_bfloat16* __restrict__ Cl, int bm, int bn)
{
    extern __shared__ __align__(16) uint8_t dsm[];
    const uint32_t sb = smem_u32(dsm);

    const int tid = threadIdx.x, wid = tid >> 5, lane = tid & 31;
    const int wm = (wid & 3) * 32, wn = (wid >> 2) * 32;
    const int lrow = lane & 15, lch = lane >> 4;

    float acc[2][4][4] = {};

#define ISSUE(c, st) do {                                                      \
    uint32_t stb = sb + (st) * STAGE_B;                                        \
    _Pragma("unroll")                                                          \
    for (int i = 0; i < 4; i++) {                                              \
        int u = tid + i * 256; int arr = u >> 9; int rem = u & 511;            \
        int row = rem >> 2, un = rem & 3;                                      \
        const __nv_bfloat16* gp = (arr ? Al : Ah) +                            \
            (size_t)(bm + row) * CS + (c) * 32 + un * 8;                       \
        cpa16(stb + arr * SA_BYTES + row * ASTR + un * 16, gp);                \
    }                                                                          \
    _Pragma("unroll")                                                          \
    for (int i = 0; i < 2; i++) {                                              \
        int u = tid + i * 256; int arr = u >> 8; int rem = u & 255;            \
        int row = rem >> 2, un = rem & 3;                                      \
        const __nv_bfloat16* gp = (arr ? Bl : Bh) +                            \
            (size_t)(bn + row) * CS + (c) * 32 + un * 8;                       \
        cpa16(stb + 2 * SA_BYTES + arr * SB_BYTES + row * ASTR + un * 16, gp); \
    } } while (0)

    ISSUE(0, 0); cpa_commit();

    for (int c = 0; c < 32; c++) {
        const int st = c & 1;
        if (c < 31) { ISSUE(c + 1, st ^ 1); cpa_commit(); cpa_wait<1>(); }
        else cpa_wait<0>();
        __syncthreads();

        const uint32_t stb = sb + st * STAGE_B;
#pragma unroll
        for (int kh = 0; kh < 2; kh++) {
            uint32_t Af[2][4], Af2[2][4], Bf[2][4], Bf2[2][4];
#pragma unroll
            for (int mf = 0; mf < 2; mf++) {
                uint32_t off = (uint32_t)((wm + mf * 16 + lrow) * ASTR + kh * 32 + lch * 16);
                ldsm4(Af[mf],  stb + off);
                ldsm4(Af2[mf], stb + SA_BYTES + off);
            }
#pragma unroll
            for (int gi = 0; gi < 2; gi++) {
                uint32_t off = (uint32_t)((wn + gi * 16 + lrow) * ASTR + kh * 32 + lch * 16);
                ldsm4(Bf[gi],  stb + 2 * SA_BYTES + off);
                ldsm4(Bf2[gi], stb + 2 * SA_BYTES + SB_BYTES + off);
            }
#pragma unroll
            for (int mf = 0; mf < 2; mf++)
#pragma unroll
                for (int nf = 0; nf < 4; nf++) {
                    int gi = nf >> 1, s2 = nf & 1;
                    mma_bf16(acc[mf][nf], Af[mf],  Bf[gi][s2],  Bf[gi][s2 + 2]);
                    mma_bf16(acc[mf][nf], Af[mf],  Bf2[gi][s2], Bf2[gi][s2 + 2]);
                    mma_bf16(acc[mf][nf], Af2[mf], Bf[gi][s2],  Bf[gi][s2 + 2]);
                }
        }
        __syncthreads();
    }
#undef ISSUE

#pragma unroll
    for (int mf = 0; mf < 2; mf++)
#pragma unroll
        for (int nf = 0; nf < 4; nf++) {
            int col = bn + wn + nf * 8 + (lane & 3) * 2;
#pragma unroll
            for (int rh = 0; rh < 2; rh++) {
                int row = bm + wm + mf * 16 + (lane >> 2) + rh * 8;
                float v0 = acc[mf][nf][rh * 2 + 0];
                float v1 = acc[mf][nf][rh * 2 + 1];
                if (mode == EP_PAIR_BIAS) { v0 += bias[col]; v1 += bias[col + 1]; }
                if (mode == EP_F32_SIG) {
                    v0 = 1.0f / (1.0f + __expf(-v0));
                    v1 = 1.0f / (1.0f + __expf(-v1));
                }
                if (mode == EP_F32 || mode == EP_F32_SIG) {
                    float2 st2; st2.x = v0; st2.y = v1;
                    *(float2*)(Cf + (size_t)row * CS + col) = st2;
                } else {
                    uint32_t hp, lp; split2(v0, v1, &hp, &lp);
                    *(uint32_t*)(Ch + (size_t)row * CS + col) = hp;
                    *(uint32_t*)(Cl + (size_t)row * CS + col) = lp;
                }
            }
        }
}

__global__ __launch_bounds__(256, 2) void mma_proj(
    const float* __restrict__ bq)
{
    switch (blockIdx.z) {
        case 0:
            gemm_bf16_body(g_sh, g_sl, g_Wqh, g_Wql, bq, EP_PAIR_BIAS,
                           nullptr, g_qh, g_ql, blockIdx.y * 128, blockIdx.x * 64);
            break;
        case 1:
            gemm_bf16_body(g_kih, g_kil, g_Wkh, g_Wkl, nullptr, EP_PAIR,
                           nullptr, g_kh, g_kl, blockIdx.y * 128, blockIdx.x * 64);
            break;
        case 2:
            gemm_bf16_body(g_kih, g_kil, g_Wvh, g_Wvl, nullptr, EP_PAIR,
                           nullptr, g_vh, g_vl, blockIdx.y * 128, blockIdx.x * 64);
            break;
        default:
            gemm_bf16_body(g_sh, g_sl, g_Wgh, g_Wgl, nullptr, EP_F32_SIG,
                           g_gt, nullptr, nullptr, blockIdx.y * 128, blockIdx.x * 64);
            break;
    }
}

__global__ __launch_bounds__(256, 2) void mma_gated(float* __restrict__ out)
{
    gemm_bf16_body(g_goh, g_gol, g_Woh, g_Wol, nullptr, EP_F32,
                   out, nullptr, nullptr, blockIdx.y * 128, blockIdx.x * 64);
}

// ============ z projection via mma: z[h][m] = bias[m,:].Wz[:,h] + mask =====
#define WSTR 272

__global__ __launch_bounds__(128) void z_mma(
    const float* __restrict__ bias, const float* __restrict__ Wz,
    const float* __restrict__ mask, float* __restrict__ z)
{
    __shared__ __align__(16) uint8_t sAh[128 * ASTR], sAl[128 * ASTR];
    __shared__ __align__(16) uint8_t sWh[16 * WSTR],  sWl[16 * WSTR];

    const int tid = threadIdx.x, wid = tid >> 5, lane = tid & 31;
    const size_t bm = (size_t)blockIdx.x * 128;
    const int wm = wid * 32;
    const int lrow = lane & 15, lch = lane >> 4;

#pragma unroll
    for (int i = 0; i < 16; i++) {
        int idx = tid + i * 128;
        int h = idx >> 7, c = idx & 127;
        float v = Wz[c * NH + h];
        __nv_bfloat16 hb = __float2bfloat16_rn(v);
        *(uint16_t*)(sWh + h * WSTR + c * 2) = __bfloat16_as_ushort(hb);
        *(uint16_t*)(sWl + h * WSTR + c * 2) =
            __bfloat16_as_ushort(__float2bfloat16_rn(v - __bfloat162float(hb)));
    }

    float acc[2][2][4] = {};
    float4 ra[8];

#define ZLOAD(c) do {                                                          \
    _Pragma("unroll")                                                          \
    for (int i = 0; i < 8; i++) {                                              \
        int slot = tid + i * 128; int row = slot >> 3, qq = slot & 7;          \
        ra[i] = *(const float4*)(bias + (bm + row) * CZ + (c) * 32 + qq * 4);  \
    } } while (0)

    ZLOAD(0);
    for (int c = 0; c < 4; c++) {
        __syncthreads();
#pragma unroll
        for (int i = 0; i < 8; i++) {
            int slot = tid + i * 128; int row = slot >> 3, qq = slot & 7;
            uint2 hi, lo; split4(ra[i], &hi, &lo);
            *(uint2*)(sAh + row * ASTR + qq * 8) = hi;
            *(uint2*)(sAl + row * ASTR + qq * 8) = lo;
        }
        __syncthreads();
        if (c < 3) ZLOAD(c + 1);

#pragma unroll
        for (int kh = 0; kh < 2; kh++) {
            uint32_t Wh[4], Wl[4];
            uint32_t woff = (uint32_t)(lrow * WSTR + c * 64 + kh * 32 + lch * 16);
            ldsm4(Wh, smem_u32(sWh) + woff);
            ldsm4(Wl, smem_u32(sWl) + woff);
#pragma unroll
            for (int mf = 0; mf < 2; mf++) {
                uint32_t Ah[4], Al[4];
                uint32_t off = (uint32_t)((wm + mf * 16 + lrow) * ASTR + kh * 32 + lch * 16);
                ldsm4(Ah, smem_u32(sAh) + off);
                ldsm4(Al, smem_u32(sAl) + off);
#pragma unroll
                for (int nf = 0; nf < 2; nf++) {
                    mma_bf16(acc[mf][nf], Ah, Wh[nf], Wh[nf + 2]);
                    mma_bf16(acc[mf][nf], Ah, Wl[nf], Wl[nf + 2]);
                    mma_bf16(acc[mf][nf], Al, Wh[nf], Wh[nf + 2]);
                }
            }
        }
    }
#undef ZLOAD

#pragma unroll
    for (int mf = 0; mf < 2; mf++)
#pragma unroll
        for (int rh = 0; rh < 2; rh++) {
            size_t m = bm + wm + mf * 16 + (lane >> 2) + rh * 8;
            float mterm = (1.0f - mask[m & (NJ - 1)]) * (-1000000.0f);
#pragma unroll
            for (int nf = 0; nf < 2; nf++) {
                int h0 = nf * 8 + (lane & 3) * 2;
                z[(size_t)h0 * ((size_t)NI * NJ) + m]       = acc[mf][nf][rh * 2 + 0] + mterm;
                z[(size_t)(h0 + 1) * ((size_t)NI * NJ) + m] = acc[mf][nf][rh * 2 + 1] + mterm;
            }
        }
}

// ============ attention on mma.sync (bf16 q/k/v inputs) ====================
#define FSTR 144
#define LGW 1032
#define OFF_LG 0
#define OFF_QH 132096
#define OFF_QL (OFF_QH + 32 * FSTR)
#define OFF_KH (OFF_QL + 32 * FSTR)
#define OFF_KL (OFF_KH + 64 * FSTR)
#define OFF_PH (OFF_KL + 64 * FSTR)
#define OFF_PL (OFF_PH + 32 * FSTR)
#define OFF_INV (OFF_PL + 32 * FSTR)
#define ATTN_SMEM (OFF_INV + 128)

__global__ __launch_bounds__(256) void attn_mma(
    const float* __restrict__ z, float* __restrict__ dummy)
{
    extern __shared__ __align__(16) uint8_t dsm[];
    float* lg = (float*)(dsm + OFF_LG);
    float* invs = (float*)(dsm + OFF_INV);
    const uint32_t sb = smem_u32(dsm);

    const int tid = threadIdx.x, wid = tid >> 5, lane = tid & 31;
    const int i0 = blockIdx.x * 32;
    const int h  = blockIdx.y;
    const int wm = (wid & 1) * 16;
    const int wn = (wid >> 1) * 16;
    const int lrow = lane & 15, lch = lane >> 4;
    const float* zh = z + (size_t)h * ((size_t)NI * NJ);

    // load Q tile (32 x 64) bf16 hi/lo
#pragma unroll
    for (int i = 0; i < 2; i++) {
        int u = tid + i * 256; int arr = u >> 8; int rem = u & 255;
        int row = rem >> 3, un = rem & 7;
        const __nv_bfloat16* src = (arr ? g_ql : g_qh) +
            (size_t)(i0 + row) * CS + h * ND + un * 8;
        *(uint4*)(dsm + (arr ? OFF_QL : OFF_QH) + row * FSTR + un * 16) =
            *(const uint4*)src;
    }

    // ---------------- Pass A: logits ----------------
    for (int c = 0; c < 16; c++) {
        __syncthreads();
#pragma unroll
        for (int i = 0; i < 4; i++) {
            int u = tid + i * 256; int arr = u >> 9; int rem = u & 511;
            int row = rem >> 3, un = rem & 7;
            const __nv_bfloat16* src = (arr ? g_kl : g_kh) +
                (size_t)(c * 64 + row) * CS + h * ND + un * 8;
            *(uint4*)(dsm + (arr ? OFF_KL : OFF_KH) + row * FSTR + un * 16) =
                *(const uint4*)src;
        }
        __syncthreads();

        float accS[2][4] = {};
#pragma unroll
        for (int kh = 0; kh < 4; kh++) {
            uint32_t Ah[4], Al[4], Bh[4], Bl[4];
            uint32_t aoff = (uint32_t)((wm + lrow) * FSTR + kh * 32 + lch * 16);
            ldsm4(Ah, sb + OFF_QH + aoff);
            ldsm4(Al, sb + OFF_QL + aoff);
            uint32_t boff = (uint32_t)((wn + lrow) * FSTR + kh * 32 + lch * 16);
            ldsm4(Bh, sb + OFF_KH + boff);
            ldsm4(Bl, sb + OFF_KL + boff);
#pragma unroll
            for (int nf = 0; nf < 2; nf++) {
                mma_bf16(accS[nf], Ah, Bh[nf], Bh[nf + 2]);
                mma_bf16(accS[nf], Ah, Bl[nf], Bl[nf + 2]);
                mma_bf16(accS[nf], Al, Bh[nf], Bh[nf + 2]);
            }
        }
#pragma unroll
        for (int nf = 0; nf < 2; nf++) {
            int col = c * 64 + wn + nf * 8 + (lane & 3) * 2;
            int r0 = wm + (lane >> 2);
            float2 s0; s0.x = accS[nf][0] * 0.125f; s0.y = accS[nf][1] * 0.125f;
            float2 s1; s1.x = accS[nf][2] * 0.125f; s1.y = accS[nf][3] * 0.125f;
            *(float2*)&lg[(size_t)r0 * LGW + col] = s0;
            *(float2*)&lg[(size_t)(r0 + 8) * LGW + col] = s1;
        }
    }
    __syncthreads();

    // ---------------- Pass B: softmax (z added here) ----------------
#pragma unroll
    for (int t = 0; t < 4; t++) {
        int r = wid * 4 + t;
        const float* zr = zh + (size_t)(i0 + r) * NJ;
        float4 vals[8];
        float mx = -1e30f;
#pragma unroll
        for (int kk = 0; kk < 8; kk++) {
            int j = lane * 4 + kk * 128;
            float4 a = *(const float4*)&lg[(size_t)r * LGW + j];
            float4 zb = *(const float4*)&zr[j];
            a.x += zb.x; a.y += zb.y; a.z += zb.z; a.w += zb.w;
            vals[kk] = a;
            mx = fmaxf(mx, fmaxf(fmaxf(a.x, a.y), fmaxf(a.z, a.w)));
        }
#pragma unroll
        for (int s = 16; s > 0; s >>= 1)
            mx = fmaxf(mx, __shfl_xor_sync(0xffffffffu, mx, s));
        float sum = 0.f;
#pragma unroll
        for (int kk = 0; kk < 8; kk++) {
            int j = lane * 4 + kk * 128;
            float4 e;
            e.x = __expf(vals[kk].x - mx);
            e.y = __expf(vals[kk].y - mx);
            e.z = __expf(vals[kk].z - mx);
            e.w = __expf(vals[kk].w - mx);
            sum += e.x + e.y + e.z + e.w;
            *(float4*)&lg[(size_t)r * LGW + j] = e;
        }
#pragma unroll
        for (int s = 16; s > 0; s >>= 1)
            sum += __shfl_xor_sync(0xffffffffu, sum, s);
        if (lane == 0) invs[r] = 1.0f / sum;
    }

    // ---------------- Pass C: O = P V ----------------
    float accO[2][4] = {};
    for (int c = 0; c < 16; c++) {
        __syncthreads();
#pragma unroll
        for (int i = 0; i < 4; i++) {
            int u = tid + i * 256; int arr = u >> 9; int rem = u & 511;
            int row = rem >> 3, un = rem & 7;
            const __nv_bfloat16* src = (arr ? g_vl : g_vh) +
                (size_t)(c * 64 + row) * CS + h * ND + un * 8;
            *(uint4*)(dsm + (arr ? OFF_KL : OFF_KH) + row * FSTR + un * 16) =
                *(const uint4*)src;
        }
#pragma unroll
        for (int i = 0; i < 2; i++) {
            int slot = tid + i * 256; int row = slot >> 4, q4 = slot & 15;
            float4 t = *(const float4*)&lg[(size_t)row * LGW + c * 64 + q4 * 4];
            uint2 hi, lo; split4(t, &hi, &lo);
            *(uint2*)(dsm + OFF_PH + row * FSTR + q4 * 8) = hi;
            *(uint2*)(dsm + OFF_PL + row * FSTR + q4 * 8) = lo;
        }
        __syncthreads();

#pragma unroll
        for (int kh = 0; kh < 4; kh++) {
            uint32_t Ph[4], Pl[4], Vh[4], Vl[4];
            uint32_t aoff = (uint32_t)((wm + lrow) * FSTR + kh * 32 + lch * 16);
            ldsm4(Ph, sb + OFF_PH + aoff);
            ldsm4(Pl, sb + OFF_PL + aoff);
            uint32_t voff = (uint32_t)((kh * 16 + lrow) * FSTR + wn * 2 + lch * 16);
            ldsm4t(Vh, sb + OFF_KH + voff);
            ldsm4t(Vl, sb + OFF_KL + voff);
#pragma unroll
            for (int nf = 0; nf < 2; nf++) {
                mma_bf16(accO[nf], Ph, Vh[nf * 2], Vh[nf * 2 + 1]);
                mma_bf16(accO[nf], Ph, Vl[nf * 2], Vl[nf * 2 + 1]);
                mma_bf16(accO[nf], Pl, Vh[nf * 2], Vh[nf * 2 + 1]);
            }
        }
    }
    __syncthreads();

    // epilogue: o = acc/sum; go = g*o written as bf16 hi/lo
#pragma unroll
    for (int nf = 0; nf < 2; nf++) {
        int col = h * ND + wn + nf * 8 + (lane & 3) * 2;
#pragma unroll
        for (int rh = 0; rh < 2; rh++) {
            int r = wm + (lane >> 2) + rh * 8;
            float is = invs[r];
            float2 gg = *(const float2*)(g_gt + (size_t)(i0 + r) * CS + col);
            float v0 = accO[nf][rh * 2 + 0] * is * gg.x;
            float v1 = accO[nf][rh * 2 + 1] * is * gg.y;
            uint32_t hp, lp; split2(v0, v1, &hp, &lp);
            *(uint32_t*)(g_goh + (size_t)(i0 + r) * CS + col) = hp;
            *(uint32_t*)(g_gol + (size_t)(i0 + r) * CS + col) = lp;
        }
    }
    (void)dummy;
}

// ---------------------------------------------------------------------------
extern "C" void kernel_launch(void* const* d_in, const int* in_sizes, int n_in,
                              void* d_out, int out_size)
{
    (void)in_sizes; (void)n_in; (void)out_size;
    const float* s    = (const float*)d_in[0];
    const float* k_in = (const float*)d_in[1];
    const float* mask = (const float*)d_in[2];
    const float* bias = (const float*)d_in[3];
    const float* bq   = (const float*)d_in[5];
    const float* Wz   = (const float*)d_in[10];
    float* out = (float*)d_out;

    float* z;
    cudaGetSymbolAddress((void**)&z, g_z);

    cudaFuncSetAttribute(mma_proj,  cudaFuncAttributeMaxDynamicSharedMemorySize,
                         GEMM_SMEM);
    cudaFuncSetAttribute(mma_gated, cudaFuncAttributeMaxDynamicSharedMemorySize,
                         GEMM_SMEM);
    cudaFuncSetAttribute(attn_mma,  cudaFuncAttributeMaxDynamicSharedMemorySize,
                         ATTN_SMEM);

    // split inputs + weights to bf16 hi/lo once
    preconv<<<dim3(128, 7), 256>>>(s, k_in, (const float*)d_in[4],
                                   (const float*)d_in[6], (const float*)d_in[7],
                                   (const float*)d_in[8], (const float*)d_in[9]);
    // 4 projections (pure-bf16 cp.async pipeline)
    mma_proj<<<dim3(16, 8, 4), 256, GEMM_SMEM>>>(bq);
    // pair-bias projection + mask
    z_mma<<<(NI * NJ) / 128, 128>>>(bias, Wz, mask, z);
    // attention (bf16 q/k/v, epilogue emits gated bf16 pairs)
    attn_mma<<<dim3(NI / 32, NH), 256, ATTN_SMEM>>>(z, out);
    // gated output projection
    mma_gated<<<dim3(16, 8), 256, GEMM_SMEM>>>(out);
}

// round 10
// speedup vs baseline: 5.1074x; 1.2965x over previous
#include <cuda_runtime.h>
#include <cuda_bf16.h>
#include <stdint.h>
#include <math.h>

#define CS 1024
#define NI 1024
#define NJ 1024
#define NH 16
#define ND 64
#define CZ 128

// ---------------- scratch (device globals; no allocation allowed) ----------
__device__ float g_gt[NI * CS];                       // sigmoid gate (fp32)
__device__ float g_z[(size_t)NH * NI * NJ];           // pair bias [h][i*NJ+j]
// bf16 hi/lo split copies
__device__ __nv_bfloat16 g_sh[NI * CS],  g_sl[NI * CS];
__device__ __nv_bfloat16 g_kih[NJ * CS], g_kil[NJ * CS];
__device__ __nv_bfloat16 g_Wqh[CS * CS], g_Wql[CS * CS];
__device__ __nv_bfloat16 g_Wkh[CS * CS], g_Wkl[CS * CS];
__device__ __nv_bfloat16 g_Wvh[CS * CS], g_Wvl[CS * CS];
__device__ __nv_bfloat16 g_Wgh[CS * CS], g_Wgl[CS * CS];
__device__ __nv_bfloat16 g_Woh[CS * CS], g_Wol[CS * CS];
__device__ __nv_bfloat16 g_qh[NI * CS],  g_ql[NI * CS];
__device__ __nv_bfloat16 g_kh[NJ * CS],  g_kl[NJ * CS];
__device__ __nv_bfloat16 g_vh[NJ * CS],  g_vl[NJ * CS];
__device__ __nv_bfloat16 g_goh[NI * CS], g_gol[NI * CS];

// ===================== mma.sync / cp.async helpers =========================
__device__ __forceinline__ uint32_t smem_u32(const void* p) {
    uint32_t r;
    asm("{ .reg .u64 t; cvta.to.shared.u64 t, %1; cvt.u32.u64 %0, t; }"
        : "=r"(r) : "l"(p));
    return r;
}
__device__ __forceinline__ void ldsm4(uint32_t* r, uint32_t a) {
    asm volatile("ldmatrix.sync.aligned.m8n8.x4.shared.b16 {%0,%1,%2,%3}, [%4];"
                 : "=r"(r[0]), "=r"(r[1]), "=r"(r[2]), "=r"(r[3]) : "r"(a));
}
__device__ __forceinline__ void ldsm4t(uint32_t* r, uint32_t a) {
    asm volatile("ldmatrix.sync.aligned.m8n8.x4.trans.shared.b16 {%0,%1,%2,%3}, [%4];"
                 : "=r"(r[0]), "=r"(r[1]), "=r"(r[2]), "=r"(r[3]) : "r"(a));
}
__device__ __forceinline__ void mma_bf16(float* d, const uint32_t* a,
                                         uint32_t b0, uint32_t b1) {
    asm volatile(
        "mma.sync.aligned.m16n8k16.row.col.f32.bf16.bf16.f32 "
        "{%0,%1,%2,%3}, {%4,%5,%6,%7}, {%8,%9}, {%0,%1,%2,%3};"
        : "+f"(d[0]), "+f"(d[1]), "+f"(d[2]), "+f"(d[3])
        : "r"(a[0]), "r"(a[1]), "r"(a[2]), "r"(a[3]), "r"(b0), "r"(b1));
}
__device__ __forceinline__ void cpa16(uint32_t s, const void* g) {
    asm volatile("cp.async.cg.shared.global [%0], [%1], 16;" :: "r"(s), "l"(g));
}
__device__ __forceinline__ void cpa_commit() {
    asm volatile("cp.async.commit_group;");
}
template <int N> __device__ __forceinline__ void cpa_wait() {
    asm volatile("cp.async.wait_group %0;" :: "n"(N));
}
__device__ __forceinline__ uint32_t pack2(__nv_bfloat16 a, __nv_bfloat16 b) {
    return (uint32_t)__bfloat16_as_ushort(a) |
           ((uint32_t)__bfloat16_as_ushort(b) << 16);
}
__device__ __forceinline__ void split4(float4 v, uint2* hi, uint2* lo) {
    __nv_bfloat16 h0 = __float2bfloat16_rn(v.x);
    __nv_bfloat16 h1 = __float2bfloat16_rn(v.y);
    __nv_bfloat16 h2 = __float2bfloat16_rn(v.z);
    __nv_bfloat16 h3 = __float2bfloat16_rn(v.w);
    hi->x = pack2(h0, h1); hi->y = pack2(h2, h3);
    lo->x = pack2(__float2bfloat16_rn(v.x - __bfloat162float(h0)),
                  __float2bfloat16_rn(v.y - __bfloat162float(h1)));
    lo->y = pack2(__float2bfloat16_rn(v.z - __bfloat162float(h2)),
                  __float2bfloat16_rn(v.w - __bfloat162float(h3)));
}
__device__ __forceinline__ void split2(float v0, float v1,
                                       uint32_t* hp, uint32_t* lp) {
    __nv_bfloat16 h0 = __float2bfloat16_rn(v0);
    __nv_bfloat16 h1 = __float2bfloat16_rn(v1);
    *hp = pack2(h0, h1);
    *lp = pack2(__float2bfloat16_rn(v0 - __bfloat162float(h0)),
                __float2bfloat16_rn(v1 - __bfloat162float(h1)));
}

// ============ preconvert: fp32 -> bf16 hi/lo for 7 matrices (1M each) ======
__global__ __launch_bounds__(256) void preconv(
    const float* __restrict__ s, const float* __restrict__ kin,
    const float* __restrict__ Wq, const float* __restrict__ Wk,
    const float* __restrict__ Wv, const float* __restrict__ Wg,
    const float* __restrict__ Wo)
{
    const float* src; __nv_bfloat16 *dh, *dl;
    switch (blockIdx.y) {
        case 0: src = s;   dh = g_sh;  dl = g_sl;  break;
        case 1: src = kin; dh = g_kih; dl = g_kil; break;
        case 2: src = Wq;  dh = g_Wqh; dl = g_Wql; break;
        case 3: src = Wk;  dh = g_Wkh; dl = g_Wkl; break;
        case 4: src = Wv;  dh = g_Wvh; dl = g_Wvl; break;
        case 5: src = Wg;  dh = g_Wgh; dl = g_Wgl; break;
        default: src = Wo; dh = g_Woh; dl = g_Wol; break;
    }
    const int stride = gridDim.x * 256;
    for (int i = blockIdx.x * 256 + threadIdx.x; i < (CS * CS) / 4; i += stride) {
        float4 v = ((const float4*)src)[i];
        uint2 hi, lo; split4(v, &hi, &lo);
        ((uint2*)dh)[i] = hi;
        ((uint2*)dl)[i] = lo;
    }
}

// ====== bf16-split GEMM: cp.async 2-stage, pure-bf16 main loop =============
#define ASTR 80
#define SA_BYTES (128 * ASTR)
#define SB_BYTES (64 * ASTR)
#define STAGE_B (2 * SA_BYTES + 2 * SB_BYTES)
#define GEMM_SMEM (2 * STAGE_B)

#define EP_F32 0
#define EP_PAIR 1
#define EP_PAIR_BIAS 2
#define EP_F32_SIG 3

__device__ __forceinline__ void gemm_bf16_body(
    const __nv_bfloat16* __restrict__ Ah, const __nv_bfloat16* __restrict__ Al,
    const __nv_bfloat16* __restrict__ Bh, const __nv_bfloat16* __restrict__ Bl,
    const float* __restrict__ bias, int mode,
    float* __restrict__ Cf, __nv_bfloat16* __restrict__ Ch,
    __nv_bfloat16* __restrict__ Cl, int bm, int bn)
{
    extern __shared__ __align__(16) uint8_t dsm[];
    const uint32_t sb = smem_u32(dsm);

    const int tid = threadIdx.x, wid = tid >> 5, lane = tid & 31;
    const int wm = (wid & 3) * 32, wn = (wid >> 2) * 32;
    const int lrow = lane & 15, lch = lane >> 4;

    float acc[2][4][4] = {};

#define ISSUE(c, st) do {                                                      \
    uint32_t stb = sb + (st) * STAGE_B;                                        \
    _Pragma("unroll")                                                          \
    for (int i = 0; i < 4; i++) {                                              \
        int u = tid + i * 256; int arr = u >> 9; int rem = u & 511;            \
        int row = rem >> 2, un = rem & 3;                                      \
        const __nv_bfloat16* gp = (arr ? Al : Ah) +                            \
            (size_t)(bm + row) * CS + (c) * 32 + un * 8;                       \
        cpa16(stb + arr * SA_BYTES + row * ASTR + un * 16, gp);                \
    }                                                                          \
    _Pragma("unroll")                                                          \
    for (int i = 0; i < 2; i++) {                                              \
        int u = tid + i * 256; int arr = u >> 8; int rem = u & 255;            \
        int row = rem >> 2, un = rem & 3;                                      \
        const __nv_bfloat16* gp = (arr ? Bl : Bh) +                            \
            (size_t)(bn + row) * CS + (c) * 32 + un * 8;                       \
        cpa16(stb + 2 * SA_BYTES + arr * SB_BYTES + row * ASTR + un * 16, gp); \
    } } while (0)

    ISSUE(0, 0); cpa_commit();

    for (int c = 0; c < 32; c++) {
        const int st = c & 1;
        if (c < 31) { ISSUE(c + 1, st ^ 1); cpa_commit(); cpa_wait<1>(); }
        else cpa_wait<0>();
        __syncthreads();

        const uint32_t stb = sb + st * STAGE_B;
#pragma unroll
        for (int kh = 0; kh < 2; kh++) {
            uint32_t Af[2][4], Af2[2][4], Bf[2][4], Bf2[2][4];
#pragma unroll
            for (int mf = 0; mf < 2; mf++) {
                uint32_t off = (uint32_t)((wm + mf * 16 + lrow) * ASTR + kh * 32 + lch * 16);
                ldsm4(Af[mf],  stb + off);
                ldsm4(Af2[mf], stb + SA_BYTES + off);
            }
#pragma unroll
            for (int gi = 0; gi < 2; gi++) {
                uint32_t off = (uint32_t)((wn + gi * 16 + lrow) * ASTR + kh * 32 + lch * 16);
                ldsm4(Bf[gi],  stb + 2 * SA_BYTES + off);
                ldsm4(Bf2[gi], stb + 2 * SA_BYTES + SB_BYTES + off);
            }
#pragma unroll
            for (int mf = 0; mf < 2; mf++)
#pragma unroll
                for (int nf = 0; nf < 4; nf++) {
                    int gi = nf >> 1, s2 = nf & 1;
                    mma_bf16(acc[mf][nf], Af[mf],  Bf[gi][s2],  Bf[gi][s2 + 2]);
                    mma_bf16(acc[mf][nf], Af[mf],  Bf2[gi][s2], Bf2[gi][s2 + 2]);
                    mma_bf16(acc[mf][nf], Af2[mf], Bf[gi][s2],  Bf[gi][s2 + 2]);
                }
        }
        __syncthreads();
    }
#undef ISSUE

#pragma unroll
    for (int mf = 0; mf < 2; mf++)
#pragma unroll
        for (int nf = 0; nf < 4; nf++) {
            int col = bn + wn + nf * 8 + (lane & 3) * 2;
#pragma unroll
            for (int rh = 0; rh < 2; rh++) {
                int row = bm + wm + mf * 16 + (lane >> 2) + rh * 8;
                float v0 = acc[mf][nf][rh * 2 + 0];
                float v1 = acc[mf][nf][rh * 2 + 1];
                if (mode == EP_PAIR_BIAS) { v0 += bias[col]; v1 += bias[col + 1]; }
                if (mode == EP_F32_SIG) {
                    v0 = 1.0f / (1.0f + __expf(-v0));
                    v1 = 1.0f / (1.0f + __expf(-v1));
                }
                if (mode == EP_F32 || mode == EP_F32_SIG) {
                    float2 st2; st2.x = v0; st2.y = v1;
                    *(float2*)(Cf + (size_t)row * CS + col) = st2;
                } else {
                    uint32_t hp, lp; split2(v0, v1, &hp, &lp);
                    *(uint32_t*)(Ch + (size_t)row * CS + col) = hp;
                    *(uint32_t*)(Cl + (size_t)row * CS + col) = lp;
                }
            }
        }
}

__global__ __launch_bounds__(256, 2) void mma_proj(const float* __restrict__ bq)
{
    switch (blockIdx.z) {
        case 0:
            gemm_bf16_body(g_sh, g_sl, g_Wqh, g_Wql, bq, EP_PAIR_BIAS,
                           nullptr, g_qh, g_ql, blockIdx.y * 128, blockIdx.x * 64);
            break;
        case 1:
            gemm_bf16_body(g_kih, g_kil, g_Wkh, g_Wkl, nullptr, EP_PAIR,
                           nullptr, g_kh, g_kl, blockIdx.y * 128, blockIdx.x * 64);
            break;
        case 2:
            gemm_bf16_body(g_kih, g_kil, g_Wvh, g_Wvl, nullptr, EP_PAIR,
                           nullptr, g_vh, g_vl, blockIdx.y * 128, blockIdx.x * 64);
            break;
        default:
            gemm_bf16_body(g_sh, g_sl, g_Wgh, g_Wgl, nullptr, EP_F32_SIG,
                           g_gt, nullptr, nullptr, blockIdx.y * 128, blockIdx.x * 64);
            break;
    }
}

__global__ __launch_bounds__(256, 2) void mma_gated(float* __restrict__ out)
{
    gemm_bf16_body(g_goh, g_gol, g_Woh, g_Wol, nullptr, EP_F32,
                   out, nullptr, nullptr, blockIdx.y * 128, blockIdx.x * 64);
}

// ============ z projection via mma: z[h][m] = bias[m,:].Wz[:,h] + mask =====
#define WSTR 272

__global__ __launch_bounds__(128) void z_mma(
    const float* __restrict__ bias, const float* __restrict__ Wz,
    const float* __restrict__ mask, float* __restrict__ z)
{
    __shared__ __align__(16) uint8_t sAh[128 * ASTR], sAl[128 * ASTR];
    __shared__ __align__(16) uint8_t sWh[16 * WSTR],  sWl[16 * WSTR];

    const int tid = threadIdx.x, wid = tid >> 5, lane = tid & 31;
    const size_t bm = (size_t)blockIdx.x * 128;
    const int wm = wid * 32;
    const int lrow = lane & 15, lch = lane >> 4;

#pragma unroll
    for (int i = 0; i < 16; i++) {
        int idx = tid + i * 128;
        int h = idx >> 7, c = idx & 127;
        float v = Wz[c * NH + h];
        __nv_bfloat16 hb = __float2bfloat16_rn(v);
        *(uint16_t*)(sWh + h * WSTR + c * 2) = __bfloat16_as_ushort(hb);
        *(uint16_t*)(sWl + h * WSTR + c * 2) =
            __bfloat16_as_ushort(__float2bfloat16_rn(v - __bfloat162float(hb)));
    }

    float acc[2][2][4] = {};
    float4 ra[8];

#define ZLOAD(c) do {                                                          \
    _Pragma("unroll")                                                          \
    for (int i = 0; i < 8; i++) {                                              \
        int slot = tid + i * 128; int row = slot >> 3, qq = slot & 7;          \
        ra[i] = *(const float4*)(bias + (bm + row) * CZ + (c) * 32 + qq * 4);  \
    } } while (0)

    ZLOAD(0);
    for (int c = 0; c < 4; c++) {
        __syncthreads();
#pragma unroll
        for (int i = 0; i < 8; i++) {
            int slot = tid + i * 128; int row = slot >> 3, qq = slot & 7;
            uint2 hi, lo; split4(ra[i], &hi, &lo);
            *(uint2*)(sAh + row * ASTR + qq * 8) = hi;
            *(uint2*)(sAl + row * ASTR + qq * 8) = lo;
        }
        __syncthreads();
        if (c < 3) ZLOAD(c + 1);

#pragma unroll
        for (int kh = 0; kh < 2; kh++) {
            uint32_t Wh[4], Wl[4];
            uint32_t woff = (uint32_t)(lrow * WSTR + c * 64 + kh * 32 + lch * 16);
            ldsm4(Wh, smem_u32(sWh) + woff);
            ldsm4(Wl, smem_u32(sWl) + woff);
#pragma unroll
            for (int mf = 0; mf < 2; mf++) {
                uint32_t Ah[4], Al[4];
                uint32_t off = (uint32_t)((wm + mf * 16 + lrow) * ASTR + kh * 32 + lch * 16);
                ldsm4(Ah, smem_u32(sAh) + off);
                ldsm4(Al, smem_u32(sAl) + off);
#pragma unroll
                for (int nf = 0; nf < 2; nf++) {
                    mma_bf16(acc[mf][nf], Ah, Wh[nf], Wh[nf + 2]);
                    mma_bf16(acc[mf][nf], Ah, Wl[nf], Wl[nf + 2]);
                    mma_bf16(acc[mf][nf], Al, Wh[nf], Wh[nf + 2]);
                }
            }
        }
    }
#undef ZLOAD

#pragma unroll
    for (int mf = 0; mf < 2; mf++)
#pragma unroll
        for (int rh = 0; rh < 2; rh++) {
            size_t m = bm + wm + mf * 16 + (lane >> 2) + rh * 8;
            float mterm = (1.0f - mask[m & (NJ - 1)]) * (-1000000.0f);
#pragma unroll
            for (int nf = 0; nf < 2; nf++) {
                int h0 = nf * 8 + (lane & 3) * 2;
                z[(size_t)h0 * ((size_t)NI * NJ) + m]       = acc[mf][nf][rh * 2 + 0] + mterm;
                z[(size_t)(h0 + 1) * ((size_t)NI * NJ) + m] = acc[mf][nf][rh * 2 + 1] + mterm;
            }
        }
}

// ============ flash attention: block = 64 i x 1 head, 4 warps ==============
// Warp owns 16 full rows; online softmax; P repacked reg->reg; smem = K/V only.
#define FST 144
#define RG_B (64 * FST)          // 9216 per region
#define STG_B (4 * RG_B)         // Kh,Kl,Vh,Vl per stage
#define AT_SMEM (2 * STG_B)      // 73728

__global__ __launch_bounds__(128, 2) void attn_flash(const float* __restrict__ z)
{
    extern __shared__ __align__(16) uint8_t dsm[];
    const uint32_t sb = smem_u32(dsm);
    const int tid = threadIdx.x, wid = tid >> 5, lane = tid & 31;
    const int i0 = blockIdx.x * 64;
    const int h  = blockIdx.y;
    const int lrow = lane & 15, lch = lane >> 4;
    const int r   = lane >> 2;          // 0..7
    const int cq  = (lane & 3) * 2;

    // ---- Q (64x64 hi/lo) via cp.async into stage0, ldsm to registers ----
    for (int i = tid; i < 1024; i += 128) {
        int un = i & 7, row = (i >> 3) & 63, rg = i >> 9;
        const __nv_bfloat16* src = (rg ? g_ql : g_qh) +
            (size_t)(i0 + row) * CS + h * ND + un * 8;
        cpa16(sb + rg * RG_B + row * FST + un * 16, src);
    }
    cpa_commit(); cpa_wait<0>(); __syncthreads();
    uint32_t qh[4][4], ql[4][4];
#pragma unroll
    for (int kh = 0; kh < 4; kh++) {
        uint32_t off = (uint32_t)((wid * 16 + lrow) * FST + kh * 32 + lch * 16);
        ldsm4(qh[kh], sb + off);
        ldsm4(ql[kh], sb + RG_B + off);
    }
    __syncthreads();

    float accO[8][4] = {};
    float m0 = -1e30f, m1 = -1e30f, l0 = 0.f, l1 = 0.f;

#define KVISSUE(c) do {                                                        \
    uint32_t stb_ = sb + ((c) & 1) * STG_B;                                    \
    for (int i = tid; i < 2048; i += 128) {                                    \
        int un = i & 7, row = (i >> 3) & 63, rg = i >> 9;                      \
        const __nv_bfloat16* src;                                              \
        switch (rg) { case 0: src = g_kh; break; case 1: src = g_kl; break;    \
                      case 2: src = g_vh; break; default: src = g_vl; }        \
        src += (size_t)((c) * 64 + row) * CS + h * ND + un * 8;                \
        cpa16(stb_ + rg * RG_B + row * FST + un * 16, src);                    \
    } } while (0)

    KVISSUE(0); cpa_commit();
    const float* zb0 = z + (size_t)h * ((size_t)NI * NJ) +
                       (size_t)(i0 + wid * 16 + r) * NJ;
    const float* zb1 = zb0 + 8 * NJ;

    for (int c = 0; c < 16; c++) {
        if (c < 15) { KVISSUE(c + 1); cpa_commit(); cpa_wait<1>(); }
        else cpa_wait<0>();
        __syncthreads();
        const uint32_t stb = sb + (c & 1) * STG_B;

        // ---- S = Q K^T (3-term split) ----
        float accS[8][4] = {};
#pragma unroll
        for (int kh = 0; kh < 4; kh++) {
#pragma unroll
            for (int jg = 0; jg < 4; jg++) {
                uint32_t off = (uint32_t)((jg * 16 + lrow) * FST + kh * 32 + lch * 16);
                uint32_t KH[4], KL[4];
                ldsm4(KH, stb + off);
                ldsm4(KL, stb + RG_B + off);
                mma_bf16(accS[jg * 2 + 0], qh[kh], KH[0], KH[2]);
                mma_bf16(accS[jg * 2 + 1], qh[kh], KH[1], KH[3]);
                mma_bf16(accS[jg * 2 + 0], qh[kh], KL[0], KL[2]);
                mma_bf16(accS[jg * 2 + 1], qh[kh], KL[1], KL[3]);
                mma_bf16(accS[jg * 2 + 0], ql[kh], KH[0], KH[2]);
                mma_bf16(accS[jg * 2 + 1], ql[kh], KH[1], KH[3]);
            }
        }

        // ---- scale + z, chunk max ----
        float mc0 = -1e30f, mc1 = -1e30f;
#pragma unroll
        for (int nf = 0; nf < 8; nf++) {
            int col = c * 64 + nf * 8 + cq;
            float2 za = *(const float2*)(zb0 + col);
            float2 zc = *(const float2*)(zb1 + col);
            accS[nf][0] = fmaf(accS[nf][0], 0.125f, za.x);
            accS[nf][1] = fmaf(accS[nf][1], 0.125f, za.y);
            accS[nf][2] = fmaf(accS[nf][2], 0.125f, zc.x);
            accS[nf][3] = fmaf(accS[nf][3], 0.125f, zc.y);
            mc0 = fmaxf(mc0, fmaxf(accS[nf][0], accS[nf][1]));
            mc1 = fmaxf(mc1, fmaxf(accS[nf][2], accS[nf][3]));
        }
        mc0 = fmaxf(mc0, __shfl_xor_sync(0xffffffffu, mc0, 1));
        mc0 = fmaxf(mc0, __shfl_xor_sync(0xffffffffu, mc0, 2));
        mc1 = fmaxf(mc1, __shfl_xor_sync(0xffffffffu, mc1, 1));
        mc1 = fmaxf(mc1, __shfl_xor_sync(0xffffffffu, mc1, 2));
        float nm0 = fmaxf(m0, mc0), nm1 = fmaxf(m1, mc1);
        float sc0 = __expf(m0 - nm0), sc1 = __expf(m1 - nm1);
        m0 = nm0; m1 = nm1;
        l0 *= sc0; l1 *= sc1;
#pragma unroll
        for (int nf = 0; nf < 8; nf++) {
            accO[nf][0] *= sc0; accO[nf][1] *= sc0;
            accO[nf][2] *= sc1; accO[nf][3] *= sc1;
        }

        // ---- P = exp(S - m), pack A-frags hi/lo in registers ----
        uint32_t Ph[4][4], Pl[4][4];
#pragma unroll
        for (int kg = 0; kg < 4; kg++) {
#pragma unroll
            for (int half = 0; half < 2; half++) {
                int nf = kg * 2 + half;
                float p0 = __expf(accS[nf][0] - m0);
                float p1 = __expf(accS[nf][1] - m0);
                float p2 = __expf(accS[nf][2] - m1);
                float p3 = __expf(accS[nf][3] - m1);
                l0 += p0 + p1; l1 += p2 + p3;
                __nv_bfloat16 b0 = __float2bfloat16_rn(p0);
                __nv_bfloat16 b1 = __float2bfloat16_rn(p1);
                __nv_bfloat16 b2 = __float2bfloat16_rn(p2);
                __nv_bfloat16 b3 = __float2bfloat16_rn(p3);
                Ph[kg][half * 2 + 0] = pack2(b0, b1);
                Ph[kg][half * 2 + 1] = pack2(b2, b3);
                Pl[kg][half * 2 + 0] =
                    pack2(__float2bfloat16_rn(p0 - __bfloat162float(b0)),
                          __float2bfloat16_rn(p1 - __bfloat162float(b1)));
                Pl[kg][half * 2 + 1] =
                    pack2(__float2bfloat16_rn(p2 - __bfloat162float(b2)),
                          __float2bfloat16_rn(p3 - __bfloat162float(b3)));
            }
        }

        // ---- O += P V (3-term split) ----
#pragma unroll
        for (int kg = 0; kg < 4; kg++) {
#pragma unroll
            for (int ng = 0; ng < 4; ng++) {
                uint32_t voff = (uint32_t)((kg * 16 + lrow) * FST + ng * 32 + lch * 16);
                uint32_t VH[4], VL[4];
                ldsm4t(VH, stb + 2 * RG_B + voff);
                ldsm4t(VL, stb + 3 * RG_B + voff);
                mma_bf16(accO[ng * 2 + 0], Ph[kg], VH[0], VH[1]);
                mma_bf16(accO[ng * 2 + 1], Ph[kg], VH[2], VH[3]);
                mma_bf16(accO[ng * 2 + 0], Ph[kg], VL[0], VL[1]);
                mma_bf16(accO[ng * 2 + 1], Ph[kg], VL[2], VL[3]);
                mma_bf16(accO[ng * 2 + 0], Pl[kg], VH[0], VH[1]);
                mma_bf16(accO[ng * 2 + 1], Pl[kg], VH[2], VH[3]);
            }
        }
        __syncthreads();
    }
#undef KVISSUE

    // ---- finalize: quad-reduce row sums, scale, gate, split-store ----
    l0 += __shfl_xor_sync(0xffffffffu, l0, 1);
    l0 += __shfl_xor_sync(0xffffffffu, l0, 2);
    l1 += __shfl_xor_sync(0xffffffffu, l1, 1);
    l1 += __shfl_xor_sync(0xffffffffu, l1, 2);
    float il0 = 1.0f / l0, il1 = 1.0f / l1;

    const int row0 = i0 + wid * 16 + r, row1 = row0 + 8;
#pragma unroll
    for (int nf = 0; nf < 8; nf++) {
        int col = h * ND + nf * 8 + cq;
        float2 ga = *(const float2*)(g_gt + (size_t)row0 * CS + col);
        float2 gb = *(const float2*)(g_gt + (size_t)row1 * CS + col);
        uint32_t hp, lp;
        split2(accO[nf][0] * il0 * ga.x, accO[nf][1] * il0 * ga.y, &hp, &lp);
        *(uint32_t*)(g_goh + (size_t)row0 * CS + col) = hp;
        *(uint32_t*)(g_gol + (size_t)row0 * CS + col) = lp;
        split2(accO[nf][2] * il1 * gb.x, accO[nf][3] * il1 * gb.y, &hp, &lp);
        *(uint32_t*)(g_goh + (size_t)row1 * CS + col) = hp;
        *(uint32_t*)(g_gol + (size_t)row1 * CS + col) = lp;
    }
}

// ---------------------------------------------------------------------------
extern "C" void kernel_launch(void* const* d_in, const int* in_sizes, int n_in,
                              void* d_out, int out_size)
{
    (void)in_sizes; (void)n_in; (void)out_size;
    const float* s    = (const float*)d_in[0];
    const float* k_in = (const float*)d_in[1];
    const float* mask = (const float*)d_in[2];
    const float* bias = (const float*)d_in[3];
    const float* bq   = (const float*)d_in[5];
    const float* Wz   = (const float*)d_in[10];
    float* out = (float*)d_out;

    float* z;
    cudaGetSymbolAddress((void**)&z, g_z);

    cudaFuncSetAttribute(mma_proj,   cudaFuncAttributeMaxDynamicSharedMemorySize,
                         GEMM_SMEM);
    cudaFuncSetAttribute(mma_gated,  cudaFuncAttributeMaxDynamicSharedMemorySize,
                         GEMM_SMEM);
    cudaFuncSetAttribute(attn_flash, cudaFuncAttributeMaxDynamicSharedMemorySize,
                         AT_SMEM);

    // split inputs + weights to bf16 hi/lo once
    preconv<<<dim3(128, 7), 256>>>(s, k_in, (const float*)d_in[4],
                                   (const float*)d_in[6], (const float*)d_in[7],
                                   (const float*)d_in[8], (const float*)d_in[9]);
    // 4 projections (pure-bf16 cp.async pipeline)
    mma_proj<<<dim3(16, 8, 4), 256, GEMM_SMEM>>>(bq);
    // pair-bias projection + mask
    z_mma<<<(NI * NJ) / 128, 128>>>(bias, Wz, mask, z);
    // flash attention (online softmax, register-resident P)
    attn_flash<<<dim3(NI / 64, NH), 128, AT_SMEM>>>(z);
    // gated output projection
    mma_gated<<<dim3(16, 8), 256, GEMM_SMEM>>>(out);
}

// round 11
// speedup vs baseline: 5.2294x; 1.0239x over previous
#include <cuda_runtime.h>
#include <cuda_bf16.h>
#include <stdint.h>
#include <math.h>

#define CS 1024
#define NI 1024
#define NJ 1024
#define NH 16
#define ND 64
#define CZ 128

// ---------------- scratch (device globals; no allocation allowed) ----------
__device__ float g_gt[NI * CS];                       // sigmoid gate (fp32)
__device__ float g_z[(size_t)NH * NI * NJ];           // pair bias [h][i*NJ+j]
__device__ __nv_bfloat16 g_sh[NI * CS],  g_sl[NI * CS];
__device__ __nv_bfloat16 g_kih[NJ * CS], g_kil[NJ * CS];
__device__ __nv_bfloat16 g_Wqh[CS * CS], g_Wql[CS * CS];
__device__ __nv_bfloat16 g_Wkh[CS * CS], g_Wkl[CS * CS];
__device__ __nv_bfloat16 g_Wvh[CS * CS], g_Wvl[CS * CS];
__device__ __nv_bfloat16 g_Wgh[CS * CS], g_Wgl[CS * CS];
__device__ __nv_bfloat16 g_Woh[CS * CS], g_Wol[CS * CS];
__device__ __nv_bfloat16 g_qh[NI * CS],  g_ql[NI * CS];
__device__ __nv_bfloat16 g_kh[NJ * CS],  g_kl[NJ * CS];
__device__ __nv_bfloat16 g_vh[NJ * CS],  g_vl[NJ * CS];
__device__ __nv_bfloat16 g_goh[NI * CS], g_gol[NI * CS];

// ===================== mma.sync / cp.async helpers =========================
__device__ __forceinline__ uint32_t smem_u32(const void* p) {
    uint32_t r;
    asm("{ .reg .u64 t; cvta.to.shared.u64 t, %1; cvt.u32.u64 %0, t; }"
        : "=r"(r) : "l"(p));
    return r;
}
__device__ __forceinline__ void ldsm4(uint32_t* r, uint32_t a) {
    asm volatile("ldmatrix.sync.aligned.m8n8.x4.shared.b16 {%0,%1,%2,%3}, [%4];"
                 : "=r"(r[0]), "=r"(r[1]), "=r"(r[2]), "=r"(r[3]) : "r"(a));
}
__device__ __forceinline__ void ldsm4t(uint32_t* r, uint32_t a) {
    asm volatile("ldmatrix.sync.aligned.m8n8.x4.trans.shared.b16 {%0,%1,%2,%3}, [%4];"
                 : "=r"(r[0]), "=r"(r[1]), "=r"(r[2]), "=r"(r[3]) : "r"(a));
}
__device__ __forceinline__ void mma_bf16(float* d, const uint32_t* a,
                                         uint32_t b0, uint32_t b1) {
    asm volatile(
        "mma.sync.aligned.m16n8k16.row.col.f32.bf16.bf16.f32 "
        "{%0,%1,%2,%3}, {%4,%5,%6,%7}, {%8,%9}, {%0,%1,%2,%3};"
        : "+f"(d[0]), "+f"(d[1]), "+f"(d[2]), "+f"(d[3])
        : "r"(a[0]), "r"(a[1]), "r"(a[2]), "r"(a[3]), "r"(b0), "r"(b1));
}
__device__ __forceinline__ void cpa16(uint32_t s, const void* g) {
    asm volatile("cp.async.cg.shared.global [%0], [%1], 16;" :: "r"(s), "l"(g));
}
__device__ __forceinline__ void cpa_commit() {
    asm volatile("cp.async.commit_group;");
}
template <int N> __device__ __forceinline__ void cpa_wait() {
    asm volatile("cp.async.wait_group %0;" :: "n"(N));
}
__device__ __forceinline__ uint32_t pack2(__nv_bfloat16 a, __nv_bfloat16 b) {
    return (uint32_t)__bfloat16_as_ushort(a) |
           ((uint32_t)__bfloat16_as_ushort(b) << 16);
}
__device__ __forceinline__ void split4(float4 v, uint2* hi, uint2* lo) {
    __nv_bfloat16 h0 = __float2bfloat16_rn(v.x);
    __nv_bfloat16 h1 = __float2bfloat16_rn(v.y);
    __nv_bfloat16 h2 = __float2bfloat16_rn(v.z);
    __nv_bfloat16 h3 = __float2bfloat16_rn(v.w);
    hi->x = pack2(h0, h1); hi->y = pack2(h2, h3);
    lo->x = pack2(__float2bfloat16_rn(v.x - __bfloat162float(h0)),
                  __float2bfloat16_rn(v.y - __bfloat162float(h1)));
    lo->y = pack2(__float2bfloat16_rn(v.z - __bfloat162float(h2)),
                  __float2bfloat16_rn(v.w - __bfloat162float(h3)));
}
__device__ __forceinline__ void split2(float v0, float v1,
                                       uint32_t* hp, uint32_t* lp) {
    __nv_bfloat16 h0 = __float2bfloat16_rn(v0);
    __nv_bfloat16 h1 = __float2bfloat16_rn(v1);
    *hp = pack2(h0, h1);
    *lp = pack2(__float2bfloat16_rn(v0 - __bfloat162float(h0)),
                __float2bfloat16_rn(v1 - __bfloat162float(h1)));
}

// ============ preconvert: fp32 -> bf16 hi/lo for 7 matrices (1M each) ======
__global__ __launch_bounds__(256) void preconv(
    const float* __restrict__ s, const float* __restrict__ kin,
    const float* __restrict__ Wq, const float* __restrict__ Wk,
    const float* __restrict__ Wv, const float* __restrict__ Wg,
    const float* __restrict__ Wo)
{
    const float* src; __nv_bfloat16 *dh, *dl;
    switch (blockIdx.y) {
        case 0: src = s;   dh = g_sh;  dl = g_sl;  break;
        case 1: src = kin; dh = g_kih; dl = g_kil; break;
        case 2: src = Wq;  dh = g_Wqh; dl = g_Wql; break;
        case 3: src = Wk;  dh = g_Wkh; dl = g_Wkl; break;
        case 4: src = Wv;  dh = g_Wvh; dl = g_Wvl; break;
        case 5: src = Wg;  dh = g_Wgh; dl = g_Wgl; break;
        default: src = Wo; dh = g_Woh; dl = g_Wol; break;
    }
    const int stride = gridDim.x * 256;
    for (int i = blockIdx.x * 256 + threadIdx.x; i < (CS * CS) / 4; i += stride) {
        float4 v = ((const float4*)src)[i];
        uint2 hi, lo; split4(v, &hi, &lo);
        ((uint2*)dh)[i] = hi;
        ((uint2*)dl)[i] = lo;
    }
}

// ====== bf16-split GEMM (templated BN): cp.async 2-stage ===================
#define ASTR 80
#define SA_BYTES (128 * ASTR)

#define EP_F32 0
#define EP_PAIR 1
#define EP_PAIR_BIAS 2
#define EP_F32_SIG 3

template <int BN>
__device__ __forceinline__ void gemm_bf16_body(
    const __nv_bfloat16* __restrict__ Ah, const __nv_bfloat16* __restrict__ Al,
    const __nv_bfloat16* __restrict__ Bh, const __nv_bfloat16* __restrict__ Bl,
    const float* __restrict__ bias, int mode,
    float* __restrict__ Cf, __nv_bfloat16* __restrict__ Ch,
    __nv_bfloat16* __restrict__ Cl, int bm, int bn, uint8_t* dsm)
{
    constexpr int SBB = BN * ASTR;
    constexpr int STG = 2 * SA_BYTES + 2 * SBB;
    constexpr int NF = BN / 16;          // n8 tiles per warp (4 or 2)
    constexpr int GI = BN / 32;          // 16-row B groups per warp (2 or 1)
    const uint32_t sb = smem_u32(dsm);

    const int tid = threadIdx.x, wid = tid >> 5, lane = tid & 31;
    const int wm = (wid & 3) * 32, wn = (wid >> 2) * (BN / 2);
    const int lrow = lane & 15, lch = lane >> 4;

    float acc[2][NF][4];
#pragma unroll
    for (int a = 0; a < 2; a++)
#pragma unroll
        for (int b = 0; b < NF; b++)
#pragma unroll
            for (int e = 0; e < 4; e++) acc[a][b][e] = 0.f;

    auto issue = [&](int c, int st) {
        uint32_t stb = sb + st * STG;
#pragma unroll
        for (int i = 0; i < 4; i++) {
            int u = tid + i * 256; int arr = u >> 9; int rem = u & 511;
            int row = rem >> 2, un = rem & 3;
            const __nv_bfloat16* gp = (arr ? Al : Ah) +
                (size_t)(bm + row) * CS + c * 32 + un * 8;
            cpa16(stb + arr * SA_BYTES + row * ASTR + un * 16, gp);
        }
#pragma unroll
        for (int i = 0; i < BN / 32; i++) {
            int u = tid + i * 256; int arr = u / (BN * 4); int rem = u % (BN * 4);
            int row = rem >> 2, un = rem & 3;
            const __nv_bfloat16* gp = (arr ? Bl : Bh) +
                (size_t)(bn + row) * CS + c * 32 + un * 8;
            cpa16(stb + 2 * SA_BYTES + arr * SBB + row * ASTR + un * 16, gp);
        }
    };

    issue(0, 0); cpa_commit();

    for (int c = 0; c < 32; c++) {
        const int st = c & 1;
        if (c < 31) { issue(c + 1, st ^ 1); cpa_commit(); cpa_wait<1>(); }
        else cpa_wait<0>();
        __syncthreads();

        const uint32_t stb = sb + st * STG;
#pragma unroll
        for (int kh = 0; kh < 2; kh++) {
            uint32_t Af[2][4], Af2[2][4], Bf[GI][4], Bf2[GI][4];
#pragma unroll
            for (int mf = 0; mf < 2; mf++) {
                uint32_t off = (uint32_t)((wm + mf * 16 + lrow) * ASTR + kh * 32 + lch * 16);
                ldsm4(Af[mf],  stb + off);
                ldsm4(Af2[mf], stb + SA_BYTES + off);
            }
#pragma unroll
            for (int gi = 0; gi < GI; gi++) {
                uint32_t off = (uint32_t)((wn + gi * 16 + lrow) * ASTR + kh * 32 + lch * 16);
                ldsm4(Bf[gi],  stb + 2 * SA_BYTES + off);
                ldsm4(Bf2[gi], stb + 2 * SA_BYTES + SBB + off);
            }
#pragma unroll
            for (int mf = 0; mf < 2; mf++)
#pragma unroll
                for (int nf = 0; nf < NF; nf++) {
                    int gi = nf >> 1, s2 = nf & 1;
                    mma_bf16(acc[mf][nf], Af[mf],  Bf[gi][s2],  Bf[gi][s2 + 2]);
                    mma_bf16(acc[mf][nf], Af[mf],  Bf2[gi][s2], Bf2[gi][s2 + 2]);
                    mma_bf16(acc[mf][nf], Af2[mf], Bf[gi][s2],  Bf[gi][s2 + 2]);
                }
        }
        __syncthreads();
    }

#pragma unroll
    for (int mf = 0; mf < 2; mf++)
#pragma unroll
        for (int nf = 0; nf < NF; nf++) {
            int col = bn + wn + nf * 8 + (lane & 3) * 2;
#pragma unroll
            for (int rh = 0; rh < 2; rh++) {
                int row = bm + wm + mf * 16 + (lane >> 2) + rh * 8;
                float v0 = acc[mf][nf][rh * 2 + 0];
                float v1 = acc[mf][nf][rh * 2 + 1];
                if (mode == EP_PAIR_BIAS) { v0 += bias[col]; v1 += bias[col + 1]; }
                if (mode == EP_F32_SIG) {
                    v0 = 1.0f / (1.0f + __expf(-v0));
                    v1 = 1.0f / (1.0f + __expf(-v1));
                }
                if (mode == EP_F32 || mode == EP_F32_SIG) {
                    float2 st2; st2.x = v0; st2.y = v1;
                    *(float2*)(Cf + (size_t)row * CS + col) = st2;
                } else {
                    uint32_t hp, lp; split2(v0, v1, &hp, &lp);
                    *(uint32_t*)(Ch + (size_t)row * CS + col) = hp;
                    *(uint32_t*)(Cl + (size_t)row * CS + col) = lp;
                }
            }
        }
}

#define GEMM_SMEM (2 * (2 * SA_BYTES + 2 * 64 * ASTR))   // 61440 (BN=64)
#define GATED_SMEM (2 * (2 * SA_BYTES + 2 * 32 * ASTR))  // 51200 (BN=32)

// ============ z body (256 threads = two independent 128-thread groups) =====
#define ZG_BYTES (2 * 128 * ASTR + 2 * 16 * 272)   // 29184 per group

__device__ __forceinline__ void z_body256(
    uint8_t* dsm, const float* __restrict__ bias, const float* __restrict__ Wz,
    const float* __restrict__ mask, float* __restrict__ z, size_t bm0)
{
    const int tid = threadIdx.x;
    const int grp = tid >> 7;              // 0 or 1
    const int gtid = tid & 127;
    const int wid = gtid >> 5, lane = gtid & 31;
    const size_t bm = bm0 + (size_t)grp * 128;
    const int wm = wid * 32;
    const int lrow = lane & 15, lch = lane >> 4;

    uint8_t* base = dsm + grp * ZG_BYTES;
    uint8_t* sAh = base;
    uint8_t* sAl = base + 128 * ASTR;
    uint8_t* sWh = base + 2 * 128 * ASTR;
    uint8_t* sWl = base + 2 * 128 * ASTR + 16 * 272;

#pragma unroll
    for (int i = 0; i < 16; i++) {
        int idx = gtid + i * 128;
        int h = idx >> 7, c = idx & 127;
        float v = Wz[c * NH + h];
        __nv_bfloat16 hb = __float2bfloat16_rn(v);
        *(uint16_t*)(sWh + h * 272 + c * 2) = __bfloat16_as_ushort(hb);
        *(uint16_t*)(sWl + h * 272 + c * 2) =
            __bfloat16_as_ushort(__float2bfloat16_rn(v - __bfloat162float(hb)));
    }

    float acc[2][2][4] = {};
    float4 ra[8];

#define ZLOAD(c) do {                                                          \
    _Pragma("unroll")                                                          \
    for (int i = 0; i < 8; i++) {                                              \
        int slot = gtid + i * 128; int row = slot >> 3, qq = slot & 7;         \
        ra[i] = *(const float4*)(bias + (bm + row) * CZ + (c) * 32 + qq * 4);  \
    } } while (0)

    ZLOAD(0);
    for (int c = 0; c < 4; c++) {
        __syncthreads();
#pragma unroll
        for (int i = 0; i < 8; i++) {
            int slot = gtid + i * 128; int row = slot >> 3, qq = slot & 7;
            uint2 hi, lo; split4(ra[i], &hi, &lo);
            *(uint2*)(sAh + row * ASTR + qq * 8) = hi;
            *(uint2*)(sAl + row * ASTR + qq * 8) = lo;
        }
        __syncthreads();
        if (c < 3) ZLOAD(c + 1);

#pragma unroll
        for (int kh = 0; kh < 2; kh++) {
            uint32_t Wh[4], Wl[4];
            uint32_t woff = (uint32_t)(lrow * 272 + c * 64 + kh * 32 + lch * 16);
            ldsm4(Wh, smem_u32(sWh) + woff);
            ldsm4(Wl, smem_u32(sWl) + woff);
#pragma unroll
            for (int mf = 0; mf < 2; mf++) {
                uint32_t Ah[4], Al[4];
                uint32_t off = (uint32_t)((wm + mf * 16 + lrow) * ASTR + kh * 32 + lch * 16);
                ldsm4(Ah, smem_u32(sAh) + off);
                ldsm4(Al, smem_u32(sAl) + off);
#pragma unroll
                for (int nf = 0; nf < 2; nf++) {
                    mma_bf16(acc[mf][nf], Ah, Wh[nf], Wh[nf + 2]);
                    mma_bf16(acc[mf][nf], Ah, Wl[nf], Wl[nf + 2]);
                    mma_bf16(acc[mf][nf], Al, Wh[nf], Wh[nf + 2]);
                }
            }
        }
    }
#undef ZLOAD

#pragma unroll
    for (int mf = 0; mf < 2; mf++)
#pragma unroll
        for (int rh = 0; rh < 2; rh++) {
            size_t m = bm + wm + mf * 16 + (lane >> 2) + rh * 8;
            float mterm = (1.0f - mask[m & (NJ - 1)]) * (-1000000.0f);
#pragma unroll
            for (int nf = 0; nf < 2; nf++) {
                int h0 = nf * 8 + (lane & 3) * 2;
                z[(size_t)h0 * ((size_t)NI * NJ) + m]       = acc[mf][nf][rh * 2 + 0] + mterm;
                z[(size_t)(h0 + 1) * ((size_t)NI * NJ) + m] = acc[mf][nf][rh * 2 + 1] + mterm;
            }
        }
}

// ============ fused proj + z: heterogeneous blocks, one launch =============
// blocks [0,512): projection tiles (tensor-bound)
// blocks [512,4608): z projection, 256 rows each (DRAM-bound)
__global__ __launch_bounds__(256, 2) void fused_pz(
    const float* __restrict__ bq, const float* __restrict__ bias,
    const float* __restrict__ Wz, const float* __restrict__ mask,
    float* __restrict__ z)
{
    extern __shared__ __align__(16) uint8_t dsm[];
    const int t = blockIdx.x;
    if (t < 512) {
        const int pid = t >> 7, rem = t & 127;
        const int bn = (rem & 15) * 64, bm = (rem >> 4) * 128;
        switch (pid) {
            case 0:
                gemm_bf16_body<64>(g_sh, g_sl, g_Wqh, g_Wql, bq, EP_PAIR_BIAS,
                                   nullptr, g_qh, g_ql, bm, bn, dsm);
                break;
            case 1:
                gemm_bf16_body<64>(g_kih, g_kil, g_Wkh, g_Wkl, nullptr, EP_PAIR,
                                   nullptr, g_kh, g_kl, bm, bn, dsm);
                break;
            case 2:
                gemm_bf16_body<64>(g_kih, g_kil, g_Wvh, g_Wvl, nullptr, EP_PAIR,
                                   nullptr, g_vh, g_vl, bm, bn, dsm);
                break;
            default:
                gemm_bf16_body<64>(g_sh, g_sl, g_Wgh, g_Wgl, nullptr, EP_F32_SIG,
                                   g_gt, nullptr, nullptr, bm, bn, dsm);
                break;
        }
    } else {
        z_body256(dsm, bias, Wz, mask, z, (size_t)(t - 512) * 256);
    }
}

// ============ gated output projection: 128x32 tiles, 256 blocks ============
__global__ __launch_bounds__(256, 2) void mma_gated(float* __restrict__ out)
{
    extern __shared__ __align__(16) uint8_t dsm[];
    gemm_bf16_body<32>(g_goh, g_gol, g_Woh, g_Wol, nullptr, EP_F32,
                       out, nullptr, nullptr, blockIdx.y * 128, blockIdx.x * 32,
                       dsm);
}

// ============ flash attention: block = 64 i x 1 head, 4 warps ==============
#define FST 144
#define RG_B (64 * FST)
#define STG_B (4 * RG_B)
#define AT_SMEM (2 * STG_B)

__global__ __launch_bounds__(128, 2) void attn_flash(const float* __restrict__ z)
{
    extern __shared__ __align__(16) uint8_t dsm[];
    const uint32_t sb = smem_u32(dsm);
    const int tid = threadIdx.x, wid = tid >> 5, lane = tid & 31;
    const int i0 = blockIdx.x * 64;
    const int h  = blockIdx.y;
    const int lrow = lane & 15, lch = lane >> 4;
    const int r   = lane >> 2;
    const int cq  = (lane & 3) * 2;

    for (int i = tid; i < 1024; i += 128) {
        int un = i & 7, row = (i >> 3) & 63, rg = i >> 9;
        const __nv_bfloat16* src = (rg ? g_ql : g_qh) +
            (size_t)(i0 + row) * CS + h * ND + un * 8;
        cpa16(sb + rg * RG_B + row * FST + un * 16, src);
    }
    cpa_commit(); cpa_wait<0>(); __syncthreads();
    uint32_t qh[4][4], ql[4][4];
#pragma unroll
    for (int kh = 0; kh < 4; kh++) {
        uint32_t off = (uint32_t)((wid * 16 + lrow) * FST + kh * 32 + lch * 16);
        ldsm4(qh[kh], sb + off);
        ldsm4(ql[kh], sb + RG_B + off);
    }
    __syncthreads();

    float accO[8][4] = {};
    float m0 = -1e30f, m1 = -1e30f, l0 = 0.f, l1 = 0.f;

#define KVISSUE(c) do {                                                        \
    uint32_t stb_ = sb + ((c) & 1) * STG_B;                                    \
    for (int i = tid; i < 2048; i += 128) {                                    \
        int un = i & 7, row = (i >> 3) & 63, rg = i >> 9;                      \
        const __nv_bfloat16* src;                                              \
        switch (rg) { case 0: src = g_kh; break; case 1: src = g_kl; break;    \
                      case 2: src = g_vh; break; default: src = g_vl; }        \
        src += (size_t)((c) * 64 + row) * CS + h * ND + un * 8;                \
        cpa16(stb_ + rg * RG_B + row * FST + un * 16, src);                    \
    } } while (0)

    KVISSUE(0); cpa_commit();
    const float* zb0 = z + (size_t)h * ((size_t)NI * NJ) +
                       (size_t)(i0 + wid * 16 + r) * NJ;
    const float* zb1 = zb0 + 8 * NJ;

    for (int c = 0; c < 16; c++) {
        if (c < 15) { KVISSUE(c + 1); cpa_commit(); cpa_wait<1>(); }
        else cpa_wait<0>();
        __syncthreads();
        const uint32_t stb = sb + (c & 1) * STG_B;

        float accS[8][4] = {};
#pragma unroll
        for (int kh = 0; kh < 4; kh++) {
#pragma unroll
            for (int jg = 0; jg < 4; jg++) {
                uint32_t off = (uint32_t)((jg * 16 + lrow) * FST + kh * 32 + lch * 16);
                uint32_t KH[4], KL[4];
                ldsm4(KH, stb + off);
                ldsm4(KL, stb + RG_B + off);
                mma_bf16(accS[jg * 2 + 0], qh[kh], KH[0], KH[2]);
                mma_bf16(accS[jg * 2 + 1], qh[kh], KH[1], KH[3]);
                mma_bf16(accS[jg * 2 + 0], qh[kh], KL[0], KL[2]);
                mma_bf16(accS[jg * 2 + 1], qh[kh], KL[1], KL[3]);
                mma_bf16(accS[jg * 2 + 0], ql[kh], KH[0], KH[2]);
                mma_bf16(accS[jg * 2 + 1], ql[kh], KH[1], KH[3]);
            }
        }

        float mc0 = -1e30f, mc1 = -1e30f;
#pragma unroll
        for (int nf = 0; nf < 8; nf++) {
            int col = c * 64 + nf * 8 + cq;
            float2 za = *(const float2*)(zb0 + col);
            float2 zc = *(const float2*)(zb1 + col);
            accS[nf][0] = fmaf(accS[nf][0], 0.125f, za.x);
            accS[nf][1] = fmaf(accS[nf][1], 0.125f, za.y);
            accS[nf][2] = fmaf(accS[nf][2], 0.125f, zc.x);
            accS[nf][3] = fmaf(accS[nf][3], 0.125f, zc.y);
            mc0 = fmaxf(mc0, fmaxf(accS[nf][0], accS[nf][1]));
            mc1 = fmaxf(mc1, fmaxf(accS[nf][2], accS[nf][3]));
        }
        mc0 = fmaxf(mc0, __shfl_xor_sync(0xffffffffu, mc0, 1));
        mc0 = fmaxf(mc0, __shfl_xor_sync(0xffffffffu, mc0, 2));
        mc1 = fmaxf(mc1, __shfl_xor_sync(0xffffffffu, mc1, 1));
        mc1 = fmaxf(mc1, __shfl_xor_sync(0xffffffffu, mc1, 2));
        float nm0 = fmaxf(m0, mc0), nm1 = fmaxf(m1, mc1);
        float sc0 = __expf(m0 - nm0), sc1 = __expf(m1 - nm1);
        m0 = nm0; m1 = nm1;
        l0 *= sc0; l1 *= sc1;
#pragma unroll
        for (int nf = 0; nf < 8; nf++) {
            accO[nf][0] *= sc0; accO[nf][1] *= sc0;
            accO[nf][2] *= sc1; accO[nf][3] *= sc1;
        }

        uint32_t Ph[4][4], Pl[4][4];
#pragma unroll
        for (int kg = 0; kg < 4; kg++) {
#pragma unroll
            for (int half = 0; half < 2; half++) {
                int nf = kg * 2 + half;
                float p0 = __expf(accS[nf][0] - m0);
                float p1 = __expf(accS[nf][1] - m0);
                float p2 = __expf(accS[nf][2] - m1);
                float p3 = __expf(accS[nf][3] - m1);
                l0 += p0 + p1; l1 += p2 + p3;
                __nv_bfloat16 b0 = __float2bfloat16_rn(p0);
                __nv_bfloat16 b1 = __float2bfloat16_rn(p1);
                __nv_bfloat16 b2 = __float2bfloat16_rn(p2);
                __nv_bfloat16 b3 = __float2bfloat16_rn(p3);
                Ph[kg][half * 2 + 0] = pack2(b0, b1);
                Ph[kg][half * 2 + 1] = pack2(b2, b3);
                Pl[kg][half * 2 + 0] =
                    pack2(__float2bfloat16_rn(p0 - __bfloat162float(b0)),
                          __float2bfloat16_rn(p1 - __bfloat162float(b1)));
                Pl[kg][half * 2 + 1] =
                    pack2(__float2bfloat16_rn(p2 - __bfloat162float(b2)),
                          __float2bfloat16_rn(p3 - __bfloat162float(b3)));
            }
        }

#pragma unroll
        for (int kg = 0; kg < 4; kg++) {
#pragma unroll
            for (int ng = 0; ng < 4; ng++) {
                uint32_t voff = (uint32_t)((kg * 16 + lrow) * FST + ng * 32 + lch * 16);
                uint32_t VH[4], VL[4];
                ldsm4t(VH, stb + 2 * RG_B + voff);
                ldsm4t(VL, stb + 3 * RG_B + voff);
                mma_bf16(accO[ng * 2 + 0], Ph[kg], VH[0], VH[1]);
                mma_bf16(accO[ng * 2 + 1], Ph[kg], VH[2], VH[3]);
                mma_bf16(accO[ng * 2 + 0], Ph[kg], VL[0], VL[1]);
                mma_bf16(accO[ng * 2 + 1], Ph[kg], VL[2], VL[3]);
                mma_bf16(accO[ng * 2 + 0], Pl[kg], VH[0], VH[1]);
                mma_bf16(accO[ng * 2 + 1], Pl[kg], VH[2], VH[3]);
            }
        }
        __syncthreads();
    }
#undef KVISSUE

    l0 += __shfl_xor_sync(0xffffffffu, l0, 1);
    l0 += __shfl_xor_sync(0xffffffffu, l0, 2);
    l1 += __shfl_xor_sync(0xffffffffu, l1, 1);
    l1 += __shfl_xor_sync(0xffffffffu, l1, 2);
    float il0 = 1.0f / l0, il1 = 1.0f / l1;

    const int row0 = i0 + wid * 16 + r, row1 = row0 + 8;
#pragma unroll
    for (int nf = 0; nf < 8; nf++) {
        int col = h * ND + nf * 8 + cq;
        float2 ga = *(const float2*)(g_gt + (size_t)row0 * CS + col);
        float2 gb = *(const float2*)(g_gt + (size_t)row1 * CS + col);
        uint32_t hp, lp;
        split2(accO[nf][0] * il0 * ga.x, accO[nf][1] * il0 * ga.y, &hp, &lp);
        *(uint32_t*)(g_goh + (size_t)row0 * CS + col) = hp;
        *(uint32_t*)(g_gol + (size_t)row0 * CS + col) = lp;
        split2(accO[nf][2] * il1 * gb.x, accO[nf][3] * il1 * gb.y, &hp, &lp);
        *(uint32_t*)(g_goh + (size_t)row1 * CS + col) = hp;
        *(uint32_t*)(g_gol + (size_t)row1 * CS + col) = lp;
    }
}

// ---------------------------------------------------------------------------
extern "C" void kernel_launch(void* const* d_in, const int* in_sizes, int n_in,
                              void* d_out, int out_size)
{
    (void)in_sizes; (void)n_in; (void)out_size;
    const float* s    = (const float*)d_in[0];
    const float* k_in = (const float*)d_in[1];
    const float* mask = (const float*)d_in[2];
    const float* bias = (const float*)d_in[3];
    const float* bq   = (const float*)d_in[5];
    const float* Wz   = (const float*)d_in[10];
    float* out = (float*)d_out;

    float* z;
    cudaGetSymbolAddress((void**)&z, g_z);

    cudaFuncSetAttribute(fused_pz,   cudaFuncAttributeMaxDynamicSharedMemorySize,
                         GEMM_SMEM);
    cudaFuncSetAttribute(mma_gated,  cudaFuncAttributeMaxDynamicSharedMemorySize,
                         GATED_SMEM);
    cudaFuncSetAttribute(attn_flash, cudaFuncAttributeMaxDynamicSharedMemorySize,
                         AT_SMEM);

    // split inputs + weights to bf16 hi/lo once
    preconv<<<dim3(128, 7), 256>>>(s, k_in, (const float*)d_in[4],
                                   (const float*)d_in[6], (const float*)d_in[7],
                                   (const float*)d_in[8], (const float*)d_in[9]);
    // projections (tensor-bound) + z projection (DRAM-bound) co-scheduled
    fused_pz<<<512 + 4096, 256, GEMM_SMEM>>>(bq, bias, Wz, mask, z);
    // flash attention (online softmax, register-resident P)
    attn_flash<<<dim3(NI / 64, NH), 128, AT_SMEM>>>(z);
    // gated output projection (256 blocks, 128x32 tiles)
    mma_gated<<<dim3(32, 8), 256, GATED_SMEM>>>(out);
}